// round 1
// baseline (speedup 1.0000x reference)
#include <cuda_runtime.h>
#include <cuda_bf16.h>

// Problem constants
#define CHID   256
#define HWSZ   4096      // 64*64
#define BATCH  16

typedef unsigned long long ull;

// ---------------- scratch (device globals: allocation-free) ----------------
__device__ float g_h[BATCH * CHID * HWSZ];   // after pre_conv+BN+ReLU
__device__ float g_s[BATCH * CHID * HWSZ];   // after combined depthwise
__device__ float g_t[BATCH * CHID * HWSZ];   // after pw_conv+BN+ReLU
__device__ float g_W1[CHID * CHID];
__device__ float g_W2[CHID * CHID];
__device__ float g_W3[CHID * CHID];
__device__ float g_b1[CHID], g_b2[CHID], g_b3[CHID];
__device__ float g_Wd[CHID * 81];            // combined 9x9 depthwise (incl. identity)
__device__ float g_bd[CHID];                 // combined depthwise bias

// ---------------- packed f32x2 helpers ----------------
__device__ __forceinline__ ull pack2(float x) {
    ull r;
    asm("mov.b64 %0, {%1, %1};" : "=l"(r) : "f"(x));
    return r;
}
__device__ __forceinline__ ull ffma2(ull a, ull b, ull c) {
    ull d;
    asm("fma.rn.f32x2 %0, %1, %2, %3;" : "=l"(d) : "l"(a), "l"(b), "l"(c));
    return d;
}

// ---------------- prep: fold BN into 1x1 weights; combine depthwise ----------------
__global__ void prep_kernel(
    const float* __restrict__ pre_w,
    const float* __restrict__ bn1_g, const float* __restrict__ bn1_b,
    const float* __restrict__ bn1_m, const float* __restrict__ bn1_v,
    const float* __restrict__ dw3_w, const float* __restrict__ dw3_b,
    const float* __restrict__ dw5_w, const float* __restrict__ dw5_b,
    const float* __restrict__ dw7_w, const float* __restrict__ dw7_b,
    const float* __restrict__ dw9_w, const float* __restrict__ dw9_b,
    const float* __restrict__ pw_w,
    const float* __restrict__ bn2_g, const float* __restrict__ bn2_b,
    const float* __restrict__ bn2_m, const float* __restrict__ bn2_v,
    const float* __restrict__ post_w,
    const float* __restrict__ bn3_g, const float* __restrict__ bn3_b,
    const float* __restrict__ bn3_m, const float* __restrict__ bn3_v)
{
    const int o = threadIdx.x;             // 256 threads, one output channel each
    const float EPS = 1e-5f;

    float s1 = bn1_g[o] * rsqrtf(bn1_v[o] + EPS);
    float s2 = bn2_g[o] * rsqrtf(bn2_v[o] + EPS);
    float s3 = bn3_g[o] * rsqrtf(bn3_v[o] + EPS);
    g_b1[o] = bn1_b[o] - bn1_m[o] * s1;
    g_b2[o] = bn2_b[o] - bn2_m[o] * s2;
    g_b3[o] = bn3_b[o] - bn3_m[o] * s3;

    for (int i = 0; i < CHID; i++) {
        g_W1[o * CHID + i] = pre_w [o * CHID + i] * s1;
        g_W2[o * CHID + i] = pw_w  [o * CHID + i] * s2;
        g_W3[o * CHID + i] = post_w[o * CHID + i] * s3;
    }

    // Combined 9x9 depthwise kernel: identity + dw3 + dw5 + dw7 + dw9 (all same-padded)
    float wd[81];
    #pragma unroll
    for (int i = 0; i < 81; i++) wd[i] = 0.f;
    wd[4 * 9 + 4] = 1.0f;  // identity branch
    for (int dy = 0; dy < 3; dy++)
        for (int dx = 0; dx < 3; dx++)
            wd[(3 + dy) * 9 + (3 + dx)] += dw3_w[o * 9 + dy * 3 + dx];
    for (int dy = 0; dy < 5; dy++)
        for (int dx = 0; dx < 5; dx++)
            wd[(2 + dy) * 9 + (2 + dx)] += dw5_w[o * 25 + dy * 5 + dx];
    for (int dy = 0; dy < 7; dy++)
        for (int dx = 0; dx < 7; dx++)
            wd[(1 + dy) * 9 + (1 + dx)] += dw7_w[o * 49 + dy * 7 + dx];
    for (int dy = 0; dy < 9; dy++)
        for (int dx = 0; dx < 9; dx++)
            wd[dy * 9 + dx] += dw9_w[o * 81 + dy * 9 + dx];
    for (int i = 0; i < 81; i++) g_Wd[o * 81 + i] = wd[i];

    g_bd[o] = dw3_b[o] + dw5_b[o] + dw7_b[o] + dw9_b[o];
}

// ---------------- GEMM (1x1 conv) + bias + ReLU ----------------
// C[256 x 4096] = A[256 x 256] @ B[256 x 4096], per batch (blockIdx.z)
// BM=BN=128, BK=8, 256 threads, 8x8 microtile, packed f32x2 accumulation.
__global__ __launch_bounds__(256, 2)
void gemm_bias_relu(const float* __restrict__ A, const float* __restrict__ Bg,
                    const float* __restrict__ bias, float* __restrict__ Cg)
{
    const int K = CHID, N = HWSZ;
    const float* Bp = Bg + (size_t)blockIdx.z * CHID * HWSZ;
    float*       Cp = Cg + (size_t)blockIdx.z * CHID * HWSZ;
    const int m0 = blockIdx.y * 128;
    const int n0 = blockIdx.x * 128;

    __shared__ float As[8][128];
    __shared__ float Bs[8][128];

    const int tid = threadIdx.x;
    const int a_m = tid >> 1;             // 128 rows, 2 threads per row
    const int a_k = (tid & 1) * 4;
    const int b_k = tid >> 5;             // 8 k-rows, 32 threads per row
    const int b_n = (tid & 31) * 4;
    const int m_base = (tid >> 4) * 8;    // 16 row-groups
    const int n_base = (tid & 15) * 8;    // 16 col-groups

    ull acc[8][4];
    #pragma unroll
    for (int m = 0; m < 8; m++)
        #pragma unroll
        for (int p = 0; p < 4; p++) acc[m][p] = 0ULL;

    for (int k0 = 0; k0 < K; k0 += 8) {
        float4 av = *(const float4*)(A + (size_t)(m0 + a_m) * K + k0 + a_k);
        As[a_k + 0][a_m] = av.x;
        As[a_k + 1][a_m] = av.y;
        As[a_k + 2][a_m] = av.z;
        As[a_k + 3][a_m] = av.w;
        *(float4*)(&Bs[b_k][b_n]) =
            *(const float4*)(Bp + (size_t)(k0 + b_k) * N + n0 + b_n);
        __syncthreads();

        #pragma unroll
        for (int k = 0; k < 8; k++) {
            float a[8];
            *(float4*)(a)     = *(const float4*)(&As[k][m_base]);
            *(float4*)(a + 4) = *(const float4*)(&As[k][m_base + 4]);
            ull b[4];
            const ull* bp = (const ull*)(&Bs[k][n_base]);
            b[0] = bp[0]; b[1] = bp[1]; b[2] = bp[2]; b[3] = bp[3];
            #pragma unroll
            for (int m = 0; m < 8; m++) {
                ull ap = pack2(a[m]);
                #pragma unroll
                for (int p = 0; p < 4; p++)
                    acc[m][p] = ffma2(ap, b[p], acc[m][p]);
            }
        }
        __syncthreads();
    }

    #pragma unroll
    for (int m = 0; m < 8; m++) {
        const int row = m0 + m_base + m;
        const float bv = bias[row];
        float out[8];
        #pragma unroll
        for (int p = 0; p < 4; p++) {
            union { ull u; float2 f; } cv;
            cv.u = acc[m][p];
            out[2 * p]     = fmaxf(cv.f.x + bv, 0.f);
            out[2 * p + 1] = fmaxf(cv.f.y + bv, 0.f);
        }
        *(float4*)(Cp + (size_t)row * N + n0 + n_base)     = *(float4*)(out);
        *(float4*)(Cp + (size_t)row * N + n0 + n_base + 4) = *(float4*)(out + 4);
    }
}

// ---------------- combined 9x9 depthwise (zero-padded) + bias ----------------
// One block per (channel, batch) plane; 72x72 smem tile with 4-wide halo.
__global__ __launch_bounds__(256)
void dw_combined(const float* __restrict__ H, float* __restrict__ S)
{
    const int c = blockIdx.x;
    const int b = blockIdx.y;
    const float* hp = H + ((size_t)b * CHID + c) * HWSZ;
    float*       sp = S + ((size_t)b * CHID + c) * HWSZ;

    __shared__ float tile[72][72];
    __shared__ float w[81];

    const int tid = threadIdx.x;
    for (int i = tid; i < 72 * 72; i += 256) (&tile[0][0])[i] = 0.f;
    if (tid < 81) w[tid] = g_Wd[c * 81 + tid];
    __syncthreads();
    // fill interior [4..67][4..67]
    for (int i = tid; i < 1024; i += 256) {
        const int y  = i >> 4;
        const int x4 = (i & 15) << 2;
        *(float4*)(&tile[4 + y][4 + x4]) = *(const float4*)(hp + y * 64 + x4);
    }
    __syncthreads();

    const float bd = g_bd[c];
    const int x0 = (tid & 15) * 4;
    const int tyg = tid >> 4;

    #pragma unroll
    for (int r = 0; r < 4; r++) {
        const int y = tyg + 16 * r;
        float acc0 = bd, acc1 = bd, acc2 = bd, acc3 = bd;
        #pragma unroll
        for (int j = 0; j < 9; j++) {
            const float* row = &tile[y + j][x0];
            float rv[12];
            *(float4*)(rv)     = *(const float4*)(row);
            *(float4*)(rv + 4) = *(const float4*)(row + 4);
            *(float4*)(rv + 8) = *(const float4*)(row + 8);
            #pragma unroll
            for (int i = 0; i < 9; i++) {
                const float wv = w[j * 9 + i];
                acc0 = fmaf(wv, rv[i],     acc0);
                acc1 = fmaf(wv, rv[i + 1], acc1);
                acc2 = fmaf(wv, rv[i + 2], acc2);
                acc3 = fmaf(wv, rv[i + 3], acc3);
            }
        }
        float4 o = make_float4(acc0, acc1, acc2, acc3);
        *(float4*)(sp + y * 64 + x0) = o;
    }
}

// ---------------- launch ----------------
extern "C" void kernel_launch(void* const* d_in, const int* in_sizes, int n_in,
                              void* d_out, int out_size)
{
    const float* x     = (const float*)d_in[0];
    const float* pre_w = (const float*)d_in[1];
    const float* bn1_g = (const float*)d_in[2];
    const float* bn1_b = (const float*)d_in[3];
    const float* bn1_m = (const float*)d_in[4];
    const float* bn1_v = (const float*)d_in[5];
    const float* dw3_w = (const float*)d_in[6];
    const float* dw3_b = (const float*)d_in[7];
    const float* dw5_w = (const float*)d_in[8];
    const float* dw5_b = (const float*)d_in[9];
    const float* dw7_w = (const float*)d_in[10];
    const float* dw7_b = (const float*)d_in[11];
    const float* dw9_w = (const float*)d_in[12];
    const float* dw9_b = (const float*)d_in[13];
    const float* pw_w  = (const float*)d_in[14];
    const float* bn2_g = (const float*)d_in[15];
    const float* bn2_b = (const float*)d_in[16];
    const float* bn2_m = (const float*)d_in[17];
    const float* bn2_v = (const float*)d_in[18];
    const float* post_w= (const float*)d_in[19];
    const float* bn3_g = (const float*)d_in[20];
    const float* bn3_b = (const float*)d_in[21];
    const float* bn3_m = (const float*)d_in[22];
    const float* bn3_v = (const float*)d_in[23];

    float *hb, *sb, *tb, *W1, *W2, *W3, *b1, *b2, *b3;
    cudaGetSymbolAddress((void**)&hb, g_h);
    cudaGetSymbolAddress((void**)&sb, g_s);
    cudaGetSymbolAddress((void**)&tb, g_t);
    cudaGetSymbolAddress((void**)&W1, g_W1);
    cudaGetSymbolAddress((void**)&W2, g_W2);
    cudaGetSymbolAddress((void**)&W3, g_W3);
    cudaGetSymbolAddress((void**)&b1, g_b1);
    cudaGetSymbolAddress((void**)&b2, g_b2);
    cudaGetSymbolAddress((void**)&b3, g_b3);

    prep_kernel<<<1, 256>>>(pre_w, bn1_g, bn1_b, bn1_m, bn1_v,
                            dw3_w, dw3_b, dw5_w, dw5_b,
                            dw7_w, dw7_b, dw9_w, dw9_b,
                            pw_w, bn2_g, bn2_b, bn2_m, bn2_v,
                            post_w, bn3_g, bn3_b, bn3_m, bn3_v);

    dim3 ggrid(HWSZ / 128, CHID / 128, BATCH);   // (32, 2, 16)
    gemm_bias_relu<<<ggrid, 256>>>(W1, x, b1, hb);

    dim3 dgrid(CHID, BATCH);                     // (256, 16)
    dw_combined<<<dgrid, 256>>>(hb, sb);

    gemm_bias_relu<<<ggrid, 256>>>(W2, sb, b2, tb);
    gemm_bias_relu<<<ggrid, 256>>>(W3, tb, b3, (float*)d_out);
}

// round 3
// speedup vs baseline: 1.0564x; 1.0564x over previous
#include <cuda_runtime.h>
#include <cuda_bf16.h>

#define CHID   256
#define HWSZ   4096
#define BATCH  16

typedef unsigned int       u32;
typedef unsigned long long u64;
typedef unsigned short     u16;
typedef __nv_bfloat16      bf16;

// ---------------- scratch (device globals) ----------------
__device__ u16 g_xh[BATCH * CHID * HWSZ];   // actA hi  (x split, then s split)
__device__ u16 g_xl[BATCH * CHID * HWSZ];   // actA lo
__device__ u16 g_yh[BATCH * CHID * HWSZ];   // actB hi  (h split, then t split)
__device__ u16 g_yl[BATCH * CHID * HWSZ];   // actB lo
__device__ u16 g_W1h[CHID * CHID], g_W1l[CHID * CHID];
__device__ u16 g_W2h[CHID * CHID], g_W2l[CHID * CHID];
__device__ u16 g_W3h[CHID * CHID], g_W3l[CHID * CHID];
__device__ float g_b1[CHID], g_b2[CHID], g_b3[CHID];
__device__ float g_Wd[CHID * 81];
__device__ float g_bd[CHID];

// ---------------- helpers ----------------
__device__ __forceinline__ u32 smem_u32(const void* p) {
    u32 a;
    asm("{ .reg .u64 t; cvta.to.shared.u64 t, %1; cvt.u32.u64 %0, t; }" : "=r"(a) : "l"(p));
    return a;
}
__device__ __forceinline__ u16 bf_bits(bf16 v) {
    union { bf16 b; u16 u; } c; c.b = v; return c.u;
}
__device__ __forceinline__ float bfu(u16 u) {
    __nv_bfloat16_raw r; r.x = u; return __bfloat162float((bf16)r);
}
__device__ __forceinline__ void split_bf(float v, u16& h, u16& l) {
    bf16 hb = __float2bfloat16(v);
    h = bf_bits(hb);
    l = bf_bits(__float2bfloat16(v - __bfloat162float(hb)));
}

__device__ __forceinline__ void cp16(u32 s, const void* g) {
    asm volatile("cp.async.cg.shared.global [%0], [%1], 16;" :: "r"(s), "l"(g) : "memory");
}
__device__ __forceinline__ void cp_commit() {
    asm volatile("cp.async.commit_group;" ::: "memory");
}
template<int N> __device__ __forceinline__ void cp_wait() {
    asm volatile("cp.async.wait_group %0;" :: "n"(N) : "memory");
}

__device__ __forceinline__ void ldsm_x4(u32* r, u32 a) {
    asm volatile("ldmatrix.sync.aligned.m8n8.x4.shared.b16 {%0,%1,%2,%3}, [%4];"
        : "=r"(r[0]), "=r"(r[1]), "=r"(r[2]), "=r"(r[3]) : "r"(a));
}
__device__ __forceinline__ void ldsm_x4_t(u32* r, u32 a) {
    asm volatile("ldmatrix.sync.aligned.m8n8.x4.trans.shared.b16 {%0,%1,%2,%3}, [%4];"
        : "=r"(r[0]), "=r"(r[1]), "=r"(r[2]), "=r"(r[3]) : "r"(a));
}
__device__ __forceinline__ void mma16816(float* c, const u32* a, const u32* b) {
    asm volatile("mma.sync.aligned.m16n8k16.row.col.f32.bf16.bf16.f32 "
        "{%0,%1,%2,%3}, {%4,%5,%6,%7}, {%8,%9}, {%0,%1,%2,%3};"
        : "+f"(c[0]), "+f"(c[1]), "+f"(c[2]), "+f"(c[3])
        : "r"(a[0]), "r"(a[1]), "r"(a[2]), "r"(a[3]), "r"(b[0]), "r"(b[1]));
}

// f32x2 for depthwise
__device__ __forceinline__ u64 pack2(float a, float b) {
    u64 r; asm("mov.b64 %0, {%1, %2};" : "=l"(r) : "f"(a), "f"(b)); return r;
}
__device__ __forceinline__ void unpack2(float& a, float& b, u64 v) {
    asm("mov.b64 {%0, %1}, %2;" : "=f"(a), "=f"(b) : "l"(v));
}
__device__ __forceinline__ u64 ffma2(u64 a, u64 b, u64 c) {
    u64 d; asm("fma.rn.f32x2 %0, %1, %2, %3;" : "=l"(d) : "l"(a), "l"(b), "l"(c)); return d;
}

// ---------------- prep ----------------
__global__ void prep_kernel(
    const float* __restrict__ pre_w,
    const float* __restrict__ bn1_g, const float* __restrict__ bn1_b,
    const float* __restrict__ bn1_m, const float* __restrict__ bn1_v,
    const float* __restrict__ dw3_w, const float* __restrict__ dw3_b,
    const float* __restrict__ dw5_w, const float* __restrict__ dw5_b,
    const float* __restrict__ dw7_w, const float* __restrict__ dw7_b,
    const float* __restrict__ dw9_w, const float* __restrict__ dw9_b,
    const float* __restrict__ pw_w,
    const float* __restrict__ bn2_g, const float* __restrict__ bn2_b,
    const float* __restrict__ bn2_m, const float* __restrict__ bn2_v,
    const float* __restrict__ post_w,
    const float* __restrict__ bn3_g, const float* __restrict__ bn3_b,
    const float* __restrict__ bn3_m, const float* __restrict__ bn3_v)
{
    const int o = threadIdx.x;
    const float EPS = 1e-5f;
    float s1 = bn1_g[o] * rsqrtf(bn1_v[o] + EPS);
    float s2 = bn2_g[o] * rsqrtf(bn2_v[o] + EPS);
    float s3 = bn3_g[o] * rsqrtf(bn3_v[o] + EPS);
    g_b1[o] = bn1_b[o] - bn1_m[o] * s1;
    g_b2[o] = bn2_b[o] - bn2_m[o] * s2;
    g_b3[o] = bn3_b[o] - bn3_m[o] * s3;

    for (int i = 0; i < CHID; i++) {
        float w1 = pre_w [o * CHID + i] * s1;
        float w2 = pw_w  [o * CHID + i] * s2;
        float w3 = post_w[o * CHID + i] * s3;
        split_bf(w1, g_W1h[o * CHID + i], g_W1l[o * CHID + i]);
        split_bf(w2, g_W2h[o * CHID + i], g_W2l[o * CHID + i]);
        split_bf(w3, g_W3h[o * CHID + i], g_W3l[o * CHID + i]);
    }

    float wd[81];
    #pragma unroll
    for (int i = 0; i < 81; i++) wd[i] = 0.f;
    wd[4 * 9 + 4] = 1.0f;   // identity branch
    for (int dy = 0; dy < 3; dy++) for (int dx = 0; dx < 3; dx++)
        wd[(3 + dy) * 9 + (3 + dx)] += dw3_w[o * 9 + dy * 3 + dx];
    for (int dy = 0; dy < 5; dy++) for (int dx = 0; dx < 5; dx++)
        wd[(2 + dy) * 9 + (2 + dx)] += dw5_w[o * 25 + dy * 5 + dx];
    for (int dy = 0; dy < 7; dy++) for (int dx = 0; dx < 7; dx++)
        wd[(1 + dy) * 9 + (1 + dx)] += dw7_w[o * 49 + dy * 7 + dx];
    for (int dy = 0; dy < 9; dy++) for (int dx = 0; dx < 9; dx++)
        wd[dy * 9 + dx] += dw9_w[o * 81 + dy * 9 + dx];
    for (int i = 0; i < 81; i++) g_Wd[o * 81 + i] = wd[i];
    g_bd[o] = dw3_b[o] + dw5_b[o] + dw7_b[o] + dw9_b[o];
}

// ---------------- fp32 -> bf16 hi/lo split ----------------
__global__ void convert_split(const float* __restrict__ X,
                              u16* __restrict__ Xh, u16* __restrict__ Xl)
{
    size_t i = (size_t)blockIdx.x * 256 + threadIdx.x;
    float4 v = ((const float4*)X)[i];
    ushort4 h, l;
    split_bf(v.x, h.x, l.x);
    split_bf(v.y, h.y, l.y);
    split_bf(v.z, h.z, l.z);
    split_bf(v.w, h.w, l.w);
    ((ushort4*)Xh)[i] = h;
    ((ushort4*)Xl)[i] = l;
}

// ---------------- HMMA GEMM ----------------
// C[256 x 4096] = W[256 x 256] @ X[256 x 4096] per batch.
// CTA tile 128x128, K-stage 32, 8 warps (2m x 4n), warp tile 64x32.
// 3-term bf16 split: Ah*Bh + Ah*Bl + Al*Bh, fp32 accum.
#define SA  80                    // A smem row stride (32 bf16 + pad)
#define SB  272                   // B smem row stride (128 bf16 + pad)
#define ASZ (128 * SA)            // 10240
#define BSZ (32 * SB)             // 8704
#define STG (2 * ASZ + 2 * BSZ)   // 37888 per stage
#define DYN_SMEM (2 * STG)        // 75776

__device__ __forceinline__ void load_stage(
    u32 sbase, const u16* __restrict__ Wh, const u16* __restrict__ Wl,
    const u16* __restrict__ Bh, const u16* __restrict__ Bl,
    int m0, int n0, int k0, int tid)
{
    #pragma unroll
    for (int i = 0; i < 2; i++) {                 // A: 128 x 32 bf16, hi+lo
        int u = tid + i * 256;
        int row = u >> 2, seg = u & 3;
        size_t g = (size_t)(m0 + row) * CHID + k0 + seg * 8;
        u32 so = sbase + row * SA + seg * 16;
        cp16(so, Wh + g);
        cp16(so + ASZ, Wl + g);
    }
    #pragma unroll
    for (int i = 0; i < 2; i++) {                 // B: 32 x 128 bf16, hi+lo
        int u = tid + i * 256;
        int row = u >> 4, seg = u & 15;
        size_t g = (size_t)(k0 + row) * HWSZ + n0 + seg * 8;
        u32 so = sbase + 2 * ASZ + row * SB + seg * 16;
        cp16(so, Bh + g);
        cp16(so + BSZ, Bl + g);
    }
}

template<int OMODE>   // 0: fp32 out, 1: bf16 hi/lo out
__global__ __launch_bounds__(256, 2)
void gemm_mma(const u16* __restrict__ Wh, const u16* __restrict__ Wl,
              const u16* __restrict__ Ah, const u16* __restrict__ Al,
              const float* __restrict__ bias,
              float* __restrict__ outF,
              u16* __restrict__ outH, u16* __restrict__ outL)
{
    extern __shared__ __align__(16) char smem[];
    const u32 sb = smem_u32(smem);
    const int tid = threadIdx.x;
    const int lane = tid & 31, w = tid >> 5;
    const int wm = w & 1, wn = w >> 1;
    const int n0 = blockIdx.x * 128;
    const int m0 = blockIdx.y * 128;
    const int b  = blockIdx.z;
    const u16* Bh = Ah + (size_t)b * CHID * HWSZ;
    const u16* Bl = Al + (size_t)b * CHID * HWSZ;

    float acc[4][4][4];
    #pragma unroll
    for (int i = 0; i < 4; i++)
        #pragma unroll
        for (int j = 0; j < 4; j++)
            #pragma unroll
            for (int p = 0; p < 4; p++) acc[i][j][p] = 0.f;

    load_stage(sb, Wh, Wl, Bh, Bl, m0, n0, 0, tid);
    cp_commit();

    // ldmatrix lane address components
    const int q  = lane >> 3, lr = lane & 7;
    const int fr = (q & 1) * 8 + lr;      // row offset within 16
    const int fc = (q >> 1) * 8;          // col offset (0 or 8)

    for (int s = 0; s < 8; s++) {
        if (s < 7) {
            load_stage(sb + ((s + 1) & 1) * STG, Wh, Wl, Bh, Bl, m0, n0, (s + 1) * 32, tid);
            cp_commit();
            cp_wait<1>();
        } else {
            cp_wait<0>();
        }
        __syncthreads();
        const u32 st = sb + (s & 1) * STG;

        #pragma unroll
        for (int ks = 0; ks < 2; ks++) {
            u32 bh[8], bl[8];
            #pragma unroll
            for (int p = 0; p < 2; p++) {
                u32 ba = st + 2 * ASZ + (ks * 16 + fr) * SB + (wn * 32 + p * 16 + fc) * 2;
                ldsm_x4_t(bh + p * 4, ba);
                ldsm_x4_t(bl + p * 4, ba + BSZ);
            }
            #pragma unroll
            for (int ms = 0; ms < 4; ms++) {
                u32 ah[4], al[4];
                u32 aa = st + (wm * 64 + ms * 16 + fr) * SA + (ks * 16 + fc) * 2;
                ldsm_x4(ah, aa);
                ldsm_x4(al, aa + ASZ);
                #pragma unroll
                for (int ns = 0; ns < 4; ns++) {
                    const u32* ph = &bh[(ns >> 1) * 4 + (ns & 1) * 2];
                    const u32* pl = &bl[(ns >> 1) * 4 + (ns & 1) * 2];
                    mma16816(acc[ms][ns], ah, ph);
                    mma16816(acc[ms][ns], ah, pl);
                    mma16816(acc[ms][ns], al, ph);
                }
            }
        }
        __syncthreads();
    }

    // epilogue: bias + relu
    const int r0 = lane >> 2, c0 = (lane & 3) * 2;
    #pragma unroll
    for (int ms = 0; ms < 4; ms++) {
        const int row = m0 + wm * 64 + ms * 16 + r0;
        const float bv0 = __ldg(bias + row);
        const float bv1 = __ldg(bias + row + 8);
        #pragma unroll
        for (int ns = 0; ns < 4; ns++) {
            const int col = n0 + wn * 32 + ns * 8 + c0;
            float v0 = fmaxf(acc[ms][ns][0] + bv0, 0.f);
            float v1 = fmaxf(acc[ms][ns][1] + bv0, 0.f);
            float v2 = fmaxf(acc[ms][ns][2] + bv1, 0.f);
            float v3 = fmaxf(acc[ms][ns][3] + bv1, 0.f);
            size_t o0 = ((size_t)b * CHID + row) * HWSZ + col;
            size_t o1 = o0 + (size_t)8 * HWSZ;
            if (OMODE == 0) {
                *(float2*)(outF + o0) = make_float2(v0, v1);
                *(float2*)(outF + o1) = make_float2(v2, v3);
            } else {
                ushort2 h0, l0, h1, l1;
                split_bf(v0, h0.x, l0.x); split_bf(v1, h0.y, l0.y);
                split_bf(v2, h1.x, l1.x); split_bf(v3, h1.y, l1.y);
                *(ushort2*)(outH + o0) = h0;
                *(ushort2*)(outL + o0) = l0;
                *(ushort2*)(outH + o1) = h1;
                *(ushort2*)(outL + o1) = l1;
            }
        }
    }
}

// ---------------- depthwise: 2 channels per f32x2 lane ----------------
__global__ __launch_bounds__(256)
void dw2(const u16* __restrict__ Hh, const u16* __restrict__ Hl,
         u16* __restrict__ Sh, u16* __restrict__ Sl)
{
    __shared__ __align__(16) float2 tile[72][72];
    __shared__ __align__(16) float2 w2[81];

    const int cp = blockIdx.x, b = blockIdx.y;
    const int c0 = cp * 2;
    const size_t base0 = ((size_t)b * CHID + c0) * HWSZ;
    const size_t base1 = base0 + HWSZ;
    const int tid = threadIdx.x;

    for (int i = tid; i < 72 * 72; i += 256) ((float2*)tile)[i] = make_float2(0.f, 0.f);
    if (tid < 81) w2[tid] = make_float2(g_Wd[c0 * 81 + tid], g_Wd[(c0 + 1) * 81 + tid]);
    __syncthreads();
    for (int i = tid; i < 1024; i += 256) {
        int y = i >> 4, x4 = (i & 15) << 2;
        ushort4 h0 = *(const ushort4*)(Hh + base0 + y * 64 + x4);
        ushort4 l0 = *(const ushort4*)(Hl + base0 + y * 64 + x4);
        ushort4 h1 = *(const ushort4*)(Hh + base1 + y * 64 + x4);
        ushort4 l1 = *(const ushort4*)(Hl + base1 + y * 64 + x4);
        tile[4 + y][4 + x4 + 0] = make_float2(bfu(h0.x) + bfu(l0.x), bfu(h1.x) + bfu(l1.x));
        tile[4 + y][4 + x4 + 1] = make_float2(bfu(h0.y) + bfu(l0.y), bfu(h1.y) + bfu(l1.y));
        tile[4 + y][4 + x4 + 2] = make_float2(bfu(h0.z) + bfu(l0.z), bfu(h1.z) + bfu(l1.z));
        tile[4 + y][4 + x4 + 3] = make_float2(bfu(h0.w) + bfu(l0.w), bfu(h1.w) + bfu(l1.w));
    }
    __syncthreads();

    const int x0 = (tid & 15) * 4;
    const int y0 = (tid >> 4) * 4;
    const u64 bd2 = pack2(g_bd[c0], g_bd[c0 + 1]);
    const u64* wq = (const u64*)w2;

    u64 acc[4][4];
    #pragma unroll
    for (int r = 0; r < 4; r++)
        #pragma unroll
        for (int p = 0; p < 4; p++) acc[r][p] = bd2;

    #pragma unroll
    for (int j = 0; j < 12; j++) {
        u64 rv[12];
        const ulonglong2* rp = (const ulonglong2*)&tile[y0 + j][x0];
        #pragma unroll
        for (int qq = 0; qq < 6; qq++) { ulonglong2 t = rp[qq]; rv[2 * qq] = t.x; rv[2 * qq + 1] = t.y; }
        #pragma unroll
        for (int r = 0; r < 4; r++) {
            const int jj = j - r;
            if (jj >= 0 && jj < 9) {
                #pragma unroll
                for (int i = 0; i < 9; i++) {
                    u64 wv = wq[jj * 9 + i];
                    acc[r][0] = ffma2(wv, rv[i + 0], acc[r][0]);
                    acc[r][1] = ffma2(wv, rv[i + 1], acc[r][1]);
                    acc[r][2] = ffma2(wv, rv[i + 2], acc[r][2]);
                    acc[r][3] = ffma2(wv, rv[i + 3], acc[r][3]);
                }
            }
        }
    }

    #pragma unroll
    for (int r = 0; r < 4; r++) {
        ushort4 h0, l0, h1, l1;
        u16* h0p = (u16*)&h0; u16* l0p = (u16*)&l0;
        u16* h1p = (u16*)&h1; u16* l1p = (u16*)&l1;
        #pragma unroll
        for (int p = 0; p < 4; p++) {
            float v0, v1;
            unpack2(v0, v1, acc[r][p]);
            split_bf(v0, h0p[p], l0p[p]);
            split_bf(v1, h1p[p], l1p[p]);
        }
        size_t o0 = base0 + (y0 + r) * 64 + x0;
        size_t o1 = o0 + HWSZ;
        *(ushort4*)(Sh + o0) = h0;
        *(ushort4*)(Sl + o0) = l0;
        *(ushort4*)(Sh + o1) = h1;
        *(ushort4*)(Sl + o1) = l1;
    }
}

// ---------------- launch ----------------
extern "C" void kernel_launch(void* const* d_in, const int* in_sizes, int n_in,
                              void* d_out, int out_size)
{
    const float* x = (const float*)d_in[0];

    u16 *xh, *xl, *yh, *yl;
    u16 *W1h, *W1l, *W2h, *W2l, *W3h, *W3l;
    float *b1, *b2, *b3;
    cudaGetSymbolAddress((void**)&xh,  g_xh);
    cudaGetSymbolAddress((void**)&xl,  g_xl);
    cudaGetSymbolAddress((void**)&yh,  g_yh);
    cudaGetSymbolAddress((void**)&yl,  g_yl);
    cudaGetSymbolAddress((void**)&W1h, g_W1h);
    cudaGetSymbolAddress((void**)&W1l, g_W1l);
    cudaGetSymbolAddress((void**)&W2h, g_W2h);
    cudaGetSymbolAddress((void**)&W2l, g_W2l);
    cudaGetSymbolAddress((void**)&W3h, g_W3h);
    cudaGetSymbolAddress((void**)&W3l, g_W3l);
    cudaGetSymbolAddress((void**)&b1,  g_b1);
    cudaGetSymbolAddress((void**)&b2,  g_b2);
    cudaGetSymbolAddress((void**)&b3,  g_b3);

    cudaFuncSetAttribute(gemm_mma<0>, cudaFuncAttributeMaxDynamicSharedMemorySize, DYN_SMEM);
    cudaFuncSetAttribute(gemm_mma<1>, cudaFuncAttributeMaxDynamicSharedMemorySize, DYN_SMEM);

    prep_kernel<<<1, 256>>>(
        (const float*)d_in[1], (const float*)d_in[2], (const float*)d_in[3],
        (const float*)d_in[4], (const float*)d_in[5],
        (const float*)d_in[6], (const float*)d_in[7], (const float*)d_in[8],
        (const float*)d_in[9], (const float*)d_in[10], (const float*)d_in[11],
        (const float*)d_in[12], (const float*)d_in[13],
        (const float*)d_in[14], (const float*)d_in[15], (const float*)d_in[16],
        (const float*)d_in[17], (const float*)d_in[18],
        (const float*)d_in[19], (const float*)d_in[20], (const float*)d_in[21],
        (const float*)d_in[22], (const float*)d_in[23]);

    // x -> bf16 hi/lo (actA)
    convert_split<<<BATCH * CHID * HWSZ / 1024, 256>>>(x, xh, xl);

    dim3 ggrid(HWSZ / 128, 2, BATCH);   // (32, 2, 16)

    // layer 1: h = relu(W1 @ x + b1) -> actB hi/lo
    gemm_mma<1><<<ggrid, 256, DYN_SMEM>>>(W1h, W1l, xh, xl, b1, nullptr, yh, yl);

    // depthwise: s = h + sum dw_k(h) + b -> actA hi/lo
    dim3 dgrid(CHID / 2, BATCH);        // (128, 16)
    dw2<<<dgrid, 256>>>(yh, yl, xh, xl);

    // layer 2: t = relu(W2 @ s + b2) -> actB hi/lo
    gemm_mma<1><<<ggrid, 256, DYN_SMEM>>>(W2h, W2l, xh, xl, b2, nullptr, yh, yl);

    // layer 3: out = relu(W3 @ t + b3) -> fp32 d_out
    gemm_mma<0><<<ggrid, 256, DYN_SMEM>>>(W3h, W3l, yh, yl, b3, (float*)d_out, nullptr, nullptr);
}

// round 7
// speedup vs baseline: 2.6504x; 2.5089x over previous
#include <cuda_runtime.h>
#include <cuda_bf16.h>

#define CHID   256
#define HWSZ   4096
#define BATCH  16

typedef unsigned int       u32;
typedef unsigned long long u64;
typedef unsigned short     u16;
typedef __nv_bfloat16      bf16;

// ---------------- scratch (device globals) ----------------
__device__ u16 g_xh[BATCH * CHID * HWSZ];   // actA hi  (x split, then s split)
__device__ u16 g_xl[BATCH * CHID * HWSZ];   // actA lo
__device__ u16 g_yh[BATCH * CHID * HWSZ];   // actB hi  (h split, then t split)
__device__ u16 g_yl[BATCH * CHID * HWSZ];   // actB lo
__device__ u16 g_W1h[CHID * CHID], g_W1l[CHID * CHID];
__device__ u16 g_W2h[CHID * CHID], g_W2l[CHID * CHID];
__device__ u16 g_W3h[CHID * CHID], g_W3l[CHID * CHID];
__device__ float g_b1[CHID], g_b2[CHID], g_b3[CHID];
__device__ float g_Wd[CHID * 81];
__device__ float g_bd[CHID];

// ---------------- helpers ----------------
__device__ __forceinline__ u32 smem_u32(const void* p) {
    u32 a;
    asm("{ .reg .u64 t; cvta.to.shared.u64 t, %1; cvt.u32.u64 %0, t; }" : "=r"(a) : "l"(p));
    return a;
}
__device__ __forceinline__ u16 bf_bits(bf16 v) {
    union { bf16 b; u16 u; } c; c.b = v; return c.u;
}
__device__ __forceinline__ float bfu(u16 u) {
    __nv_bfloat16_raw r; r.x = u; return __bfloat162float((bf16)r);
}
__device__ __forceinline__ void split_bf(float v, u16& h, u16& l) {
    bf16 hb = __float2bfloat16(v);
    h = bf_bits(hb);
    l = bf_bits(__float2bfloat16(v - __bfloat162float(hb)));
}

__device__ __forceinline__ void cp16(u32 s, const void* g) {
    asm volatile("cp.async.cg.shared.global [%0], [%1], 16;" :: "r"(s), "l"(g) : "memory");
}
__device__ __forceinline__ void cp_commit() {
    asm volatile("cp.async.commit_group;" ::: "memory");
}
template<int N> __device__ __forceinline__ void cp_wait() {
    asm volatile("cp.async.wait_group %0;" :: "n"(N) : "memory");
}

__device__ __forceinline__ void ldsm_x4(u32* r, u32 a) {
    asm volatile("ldmatrix.sync.aligned.m8n8.x4.shared.b16 {%0,%1,%2,%3}, [%4];"
        : "=r"(r[0]), "=r"(r[1]), "=r"(r[2]), "=r"(r[3]) : "r"(a));
}
__device__ __forceinline__ void ldsm_x4_t(u32* r, u32 a) {
    asm volatile("ldmatrix.sync.aligned.m8n8.x4.trans.shared.b16 {%0,%1,%2,%3}, [%4];"
        : "=r"(r[0]), "=r"(r[1]), "=r"(r[2]), "=r"(r[3]) : "r"(a));
}
__device__ __forceinline__ void mma16816(float* c, const u32* a, const u32* b) {
    asm volatile("mma.sync.aligned.m16n8k16.row.col.f32.bf16.bf16.f32 "
        "{%0,%1,%2,%3}, {%4,%5,%6,%7}, {%8,%9}, {%0,%1,%2,%3};"
        : "+f"(c[0]), "+f"(c[1]), "+f"(c[2]), "+f"(c[3])
        : "r"(a[0]), "r"(a[1]), "r"(a[2]), "r"(a[3]), "r"(b[0]), "r"(b[1]));
}

// f32x2 for depthwise
__device__ __forceinline__ u64 pack2(float a, float b) {
    u64 r; asm("mov.b64 %0, {%1, %2};" : "=l"(r) : "f"(a), "f"(b)); return r;
}
__device__ __forceinline__ void unpack2(float& a, float& b, u64 v) {
    asm("mov.b64 {%0, %1}, %2;" : "=f"(a), "=f"(b) : "l"(v));
}
__device__ __forceinline__ u64 ffma2(u64 a, u64 b, u64 c) {
    u64 d; asm("fma.rn.f32x2 %0, %1, %2, %3;" : "=l"(d) : "l"(a), "l"(b), "l"(c)); return d;
}

// ---------------- prep (parallel, coalesced): one block per output channel ----------------
__global__ void prep_kernel(
    const float* __restrict__ pre_w,
    const float* __restrict__ bn1_g, const float* __restrict__ bn1_b,
    const float* __restrict__ bn1_m, const float* __restrict__ bn1_v,
    const float* __restrict__ dw3_w, const float* __restrict__ dw3_b,
    const float* __restrict__ dw5_w, const float* __restrict__ dw5_b,
    const float* __restrict__ dw7_w, const float* __restrict__ dw7_b,
    const float* __restrict__ dw9_w, const float* __restrict__ dw9_b,
    const float* __restrict__ pw_w,
    const float* __restrict__ bn2_g, const float* __restrict__ bn2_b,
    const float* __restrict__ bn2_m, const float* __restrict__ bn2_v,
    const float* __restrict__ post_w,
    const float* __restrict__ bn3_g, const float* __restrict__ bn3_b,
    const float* __restrict__ bn3_m, const float* __restrict__ bn3_v)
{
    const int o = blockIdx.x;
    const int i = threadIdx.x;
    const float EPS = 1e-5f;

    const float s1 = __ldg(bn1_g + o) * rsqrtf(__ldg(bn1_v + o) + EPS);
    const float s2 = __ldg(bn2_g + o) * rsqrtf(__ldg(bn2_v + o) + EPS);
    const float s3 = __ldg(bn3_g + o) * rsqrtf(__ldg(bn3_v + o) + EPS);

    // folded 1x1 weights, coalesced across i
    split_bf(pre_w [o * CHID + i] * s1, g_W1h[o * CHID + i], g_W1l[o * CHID + i]);
    split_bf(pw_w  [o * CHID + i] * s2, g_W2h[o * CHID + i], g_W2l[o * CHID + i]);
    split_bf(post_w[o * CHID + i] * s3, g_W3h[o * CHID + i], g_W3l[o * CHID + i]);

    if (i < 81) {
        const int y = i / 9, x = i % 9;
        float v = (i == 40) ? 1.0f : 0.0f;   // identity at center
        if (y >= 3 && y <= 5 && x >= 3 && x <= 5) v += dw3_w[o * 9  + (y - 3) * 3 + (x - 3)];
        if (y >= 2 && y <= 6 && x >= 2 && x <= 6) v += dw5_w[o * 25 + (y - 2) * 5 + (x - 2)];
        if (y >= 1 && y <= 7 && x >= 1 && x <= 7) v += dw7_w[o * 49 + (y - 1) * 7 + (x - 1)];
        v += dw9_w[o * 81 + i];
        g_Wd[o * 81 + i] = v;
    }
    if (i == 0) {
        g_b1[o] = bn1_b[o] - bn1_m[o] * s1;
        g_b2[o] = bn2_b[o] - bn2_m[o] * s2;
        g_b3[o] = bn3_b[o] - bn3_m[o] * s3;
        g_bd[o] = dw3_b[o] + dw5_b[o] + dw7_b[o] + dw9_b[o];
    }
}

// ---------------- fp32 -> bf16 hi/lo split ----------------
__global__ void convert_split(const float* __restrict__ X,
                              u16* __restrict__ Xh, u16* __restrict__ Xl)
{
    size_t i = (size_t)blockIdx.x * 256 + threadIdx.x;
    float4 v = ((const float4*)X)[i];
    ushort4 h, l;
    split_bf(v.x, h.x, l.x);
    split_bf(v.y, h.y, l.y);
    split_bf(v.z, h.z, l.z);
    split_bf(v.w, h.w, l.w);
    ((ushort4*)Xh)[i] = h;
    ((ushort4*)Xl)[i] = l;
}

// ---------------- HMMA GEMM ----------------
// C[256 x 4096] = W[256 x 256] @ X[256 x 4096] per batch.
// CTA tile 128x64, K-stage 32, 8 warps (4m x 2n), warp tile 32x32 -> 32 acc regs.
// 3-term bf16 split: Ah*Bh + Ah*Bl + Al*Bh, fp32 accum. No spills by design.
#define SA  80                    // A smem row stride bytes (32 bf16 + pad)
#define SBr 144                   // B smem row stride bytes (64 bf16 + pad)
#define ASZ (128 * SA)            // 10240
#define BSZ (32 * SBr)            // 4608
#define STG (2 * ASZ + 2 * BSZ)   // 29696 per stage
#define DYN_SMEM (2 * STG)        // 59392

__device__ __forceinline__ void load_stage(
    u32 sbase, const u16* __restrict__ Wh, const u16* __restrict__ Wl,
    const u16* __restrict__ Bh, const u16* __restrict__ Bl,
    int m0, int n0, int k0, int tid)
{
    #pragma unroll
    for (int i = 0; i < 2; i++) {                 // A: 128 x 32 bf16, hi+lo
        int u = tid + i * 256;
        int row = u >> 2, seg = u & 3;
        size_t g = (size_t)(m0 + row) * CHID + k0 + seg * 8;
        u32 so = sbase + row * SA + seg * 16;
        cp16(so, Wh + g);
        cp16(so + ASZ, Wl + g);
    }
    {                                             // B: 32 x 64 bf16, hi+lo
        int row = tid >> 3, seg = tid & 7;
        size_t g = (size_t)(k0 + row) * HWSZ + n0 + seg * 8;
        u32 so = sbase + 2 * ASZ + row * SBr + seg * 16;
        cp16(so, Bh + g);
        cp16(so + BSZ, Bl + g);
    }
}

template<int OMODE>   // 0: fp32 out, 1: bf16 hi/lo out
__global__ __launch_bounds__(256, 2)
void gemm_mma(const u16* __restrict__ Wh, const u16* __restrict__ Wl,
              const u16* __restrict__ Ah, const u16* __restrict__ Al,
              const float* __restrict__ bias,
              float* __restrict__ outF,
              u16* __restrict__ outH, u16* __restrict__ outL)
{
    extern __shared__ __align__(16) char smem[];
    const u32 sb = smem_u32(smem);
    const int tid = threadIdx.x;
    const int lane = tid & 31, w = tid >> 5;
    const int wm = w & 3, wn = w >> 2;     // 4 m-warps x 2 n-warps
    const int n0 = blockIdx.x * 64;
    const int m0 = blockIdx.y * 128;
    const int b  = blockIdx.z;
    const u16* Bh = Ah + (size_t)b * CHID * HWSZ;
    const u16* Bl = Al + (size_t)b * CHID * HWSZ;

    float acc[2][4][4];
    #pragma unroll
    for (int i = 0; i < 2; i++)
        #pragma unroll
        for (int j = 0; j < 4; j++)
            #pragma unroll
            for (int p = 0; p < 4; p++) acc[i][j][p] = 0.f;

    load_stage(sb, Wh, Wl, Bh, Bl, m0, n0, 0, tid);
    cp_commit();

    // ldmatrix lane address components
    const int q  = lane >> 3, lr = lane & 7;
    const int fr = (q & 1) * 8 + lr;      // row offset within 16
    const int fc = (q >> 1) * 8;          // col offset (0 or 8)

    for (int s = 0; s < 8; s++) {
        if (s < 7) {
            load_stage(sb + ((s + 1) & 1) * STG, Wh, Wl, Bh, Bl, m0, n0, (s + 1) * 32, tid);
            cp_commit();
            cp_wait<1>();
        } else {
            cp_wait<0>();
        }
        __syncthreads();
        const u32 st = sb + (s & 1) * STG;

        #pragma unroll
        for (int ks = 0; ks < 2; ks++) {
            u32 bh[8], bl[8];
            #pragma unroll
            for (int p = 0; p < 2; p++) {
                u32 ba = st + 2 * ASZ + (ks * 16 + fr) * SBr + (wn * 32 + p * 16 + fc) * 2;
                ldsm_x4_t(bh + p * 4, ba);
                ldsm_x4_t(bl + p * 4, ba + BSZ);
            }
            #pragma unroll
            for (int ms = 0; ms < 2; ms++) {
                u32 ah[4], al[4];
                u32 aa = st + (wm * 32 + ms * 16 + fr) * SA + (ks * 16 + fc) * 2;
                ldsm_x4(ah, aa);
                ldsm_x4(al, aa + ASZ);
                #pragma unroll
                for (int ns = 0; ns < 4; ns++) {
                    const u32* ph = &bh[(ns >> 1) * 4 + (ns & 1) * 2];
                    const u32* pl = &bl[(ns >> 1) * 4 + (ns & 1) * 2];
                    mma16816(acc[ms][ns], ah, ph);
                    mma16816(acc[ms][ns], ah, pl);
                    mma16816(acc[ms][ns], al, ph);
                }
            }
        }
        __syncthreads();
    }

    // epilogue: bias + relu
    const int r0 = lane >> 2, c0 = (lane & 3) * 2;
    #pragma unroll
    for (int ms = 0; ms < 2; ms++) {
        const int row = m0 + wm * 32 + ms * 16 + r0;
        const float bv0 = __ldg(bias + row);
        const float bv1 = __ldg(bias + row + 8);
        #pragma unroll
        for (int ns = 0; ns < 4; ns++) {
            const int col = n0 + wn * 32 + ns * 8 + c0;
            float v0 = fmaxf(acc[ms][ns][0] + bv0, 0.f);
            float v1 = fmaxf(acc[ms][ns][1] + bv0, 0.f);
            float v2 = fmaxf(acc[ms][ns][2] + bv1, 0.f);
            float v3 = fmaxf(acc[ms][ns][3] + bv1, 0.f);
            size_t o0 = ((size_t)b * CHID + row) * HWSZ + col;
            size_t o1 = o0 + (size_t)8 * HWSZ;
            if (OMODE == 0) {
                *(float2*)(outF + o0) = make_float2(v0, v1);
                *(float2*)(outF + o1) = make_float2(v2, v3);
            } else {
                ushort2 h0, l0, h1, l1;
                split_bf(v0, h0.x, l0.x); split_bf(v1, h0.y, l0.y);
                split_bf(v2, h1.x, l1.x); split_bf(v3, h1.y, l1.y);
                *(ushort2*)(outH + o0) = h0;
                *(ushort2*)(outL + o0) = l0;
                *(ushort2*)(outH + o1) = h1;
                *(ushort2*)(outL + o1) = l1;
            }
        }
    }
}

// ---------------- depthwise: 2 channels per f32x2 lane ----------------
__global__ __launch_bounds__(256)
void dw2(const u16* __restrict__ Hh, const u16* __restrict__ Hl,
         u16* __restrict__ Sh, u16* __restrict__ Sl)
{
    __shared__ __align__(16) float2 tile[72][72];
    __shared__ __align__(16) float2 w2[81];

    const int cp = blockIdx.x, b = blockIdx.y;
    const int c0 = cp * 2;
    const size_t base0 = ((size_t)b * CHID + c0) * HWSZ;
    const size_t base1 = base0 + HWSZ;
    const int tid = threadIdx.x;

    for (int i = tid; i < 72 * 72; i += 256) ((float2*)tile)[i] = make_float2(0.f, 0.f);
    if (tid < 81) w2[tid] = make_float2(g_Wd[c0 * 81 + tid], g_Wd[(c0 + 1) * 81 + tid]);
    __syncthreads();
    for (int i = tid; i < 1024; i += 256) {
        int y = i >> 4, x4 = (i & 15) << 2;
        ushort4 h0 = *(const ushort4*)(Hh + base0 + y * 64 + x4);
        ushort4 l0 = *(const ushort4*)(Hl + base0 + y * 64 + x4);
        ushort4 h1 = *(const ushort4*)(Hh + base1 + y * 64 + x4);
        ushort4 l1 = *(const ushort4*)(Hl + base1 + y * 64 + x4);
        tile[4 + y][4 + x4 + 0] = make_float2(bfu(h0.x) + bfu(l0.x), bfu(h1.x) + bfu(l1.x));
        tile[4 + y][4 + x4 + 1] = make_float2(bfu(h0.y) + bfu(l0.y), bfu(h1.y) + bfu(l1.y));
        tile[4 + y][4 + x4 + 2] = make_float2(bfu(h0.z) + bfu(l0.z), bfu(h1.z) + bfu(l1.z));
        tile[4 + y][4 + x4 + 3] = make_float2(bfu(h0.w) + bfu(l0.w), bfu(h1.w) + bfu(l1.w));
    }
    __syncthreads();

    const int x0 = (tid & 15) * 4;
    const int y0 = (tid >> 4) * 4;
    const u64 bd2 = pack2(g_bd[c0], g_bd[c0 + 1]);
    const u64* wq = (const u64*)w2;

    u64 acc[4][4];
    #pragma unroll
    for (int r = 0; r < 4; r++)
        #pragma unroll
        for (int p = 0; p < 4; p++) acc[r][p] = bd2;

    #pragma unroll
    for (int j = 0; j < 12; j++) {
        u64 rv[12];
        const ulonglong2* rp = (const ulonglong2*)&tile[y0 + j][x0];
        #pragma unroll
        for (int qq = 0; qq < 6; qq++) { ulonglong2 t = rp[qq]; rv[2 * qq] = t.x; rv[2 * qq + 1] = t.y; }
        #pragma unroll
        for (int r = 0; r < 4; r++) {
            const int jj = j - r;
            if (jj >= 0 && jj < 9) {
                #pragma unroll
                for (int i = 0; i < 9; i++) {
                    u64 wv = wq[jj * 9 + i];
                    acc[r][0] = ffma2(wv, rv[i + 0], acc[r][0]);
                    acc[r][1] = ffma2(wv, rv[i + 1], acc[r][1]);
                    acc[r][2] = ffma2(wv, rv[i + 2], acc[r][2]);
                    acc[r][3] = ffma2(wv, rv[i + 3], acc[r][3]);
                }
            }
        }
    }

    #pragma unroll
    for (int r = 0; r < 4; r++) {
        ushort4 h0, l0, h1, l1;
        u16* h0p = (u16*)&h0; u16* l0p = (u16*)&l0;
        u16* h1p = (u16*)&h1; u16* l1p = (u16*)&l1;
        #pragma unroll
        for (int p = 0; p < 4; p++) {
            float v0, v1;
            unpack2(v0, v1, acc[r][p]);
            split_bf(v0, h0p[p], l0p[p]);
            split_bf(v1, h1p[p], l1p[p]);
        }
        size_t o0 = base0 + (y0 + r) * 64 + x0;
        size_t o1 = o0 + HWSZ;
        *(ushort4*)(Sh + o0) = h0;
        *(ushort4*)(Sl + o0) = l0;
        *(ushort4*)(Sh + o1) = h1;
        *(ushort4*)(Sl + o1) = l1;
    }
}

// ---------------- launch ----------------
extern "C" void kernel_launch(void* const* d_in, const int* in_sizes, int n_in,
                              void* d_out, int out_size)
{
    const float* x = (const float*)d_in[0];

    u16 *xh, *xl, *yh, *yl;
    u16 *W1h, *W1l, *W2h, *W2l, *W3h, *W3l;
    float *b1, *b2, *b3;
    cudaGetSymbolAddress((void**)&xh,  g_xh);
    cudaGetSymbolAddress((void**)&xl,  g_xl);
    cudaGetSymbolAddress((void**)&yh,  g_yh);
    cudaGetSymbolAddress((void**)&yl,  g_yl);
    cudaGetSymbolAddress((void**)&W1h, g_W1h);
    cudaGetSymbolAddress((void**)&W1l, g_W1l);
    cudaGetSymbolAddress((void**)&W2h, g_W2h);
    cudaGetSymbolAddress((void**)&W2l, g_W2l);
    cudaGetSymbolAddress((void**)&W3h, g_W3h);
    cudaGetSymbolAddress((void**)&W3l, g_W3l);
    cudaGetSymbolAddress((void**)&b1,  g_b1);
    cudaGetSymbolAddress((void**)&b2,  g_b2);
    cudaGetSymbolAddress((void**)&b3,  g_b3);

    cudaFuncSetAttribute(gemm_mma<0>, cudaFuncAttributeMaxDynamicSharedMemorySize, DYN_SMEM);
    cudaFuncSetAttribute(gemm_mma<1>, cudaFuncAttributeMaxDynamicSharedMemorySize, DYN_SMEM);

    prep_kernel<<<CHID, 256>>>(
        (const float*)d_in[1], (const float*)d_in[2], (const float*)d_in[3],
        (const float*)d_in[4], (const float*)d_in[5],
        (const float*)d_in[6], (const float*)d_in[7], (const float*)d_in[8],
        (const float*)d_in[9], (const float*)d_in[10], (const float*)d_in[11],
        (const float*)d_in[12], (const float*)d_in[13],
        (const float*)d_in[14], (const float*)d_in[15], (const float*)d_in[16],
        (const float*)d_in[17], (const float*)d_in[18],
        (const float*)d_in[19], (const float*)d_in[20], (const float*)d_in[21],
        (const float*)d_in[22], (const float*)d_in[23]);

    // x -> bf16 hi/lo (actA)
    convert_split<<<BATCH * CHID * HWSZ / 1024, 256>>>(x, xh, xl);

    dim3 ggrid(HWSZ / 64, CHID / 128, BATCH);   // (64, 2, 16)

    // layer 1: h = relu(W1 @ x + b1) -> actB hi/lo
    gemm_mma<1><<<ggrid, 256, DYN_SMEM>>>(W1h, W1l, xh, xl, b1, nullptr, yh, yl);

    // depthwise: s = h + sum dw_k(h) + b -> actA hi/lo
    dim3 dgrid(CHID / 2, BATCH);        // (128, 16)
    dw2<<<dgrid, 256>>>(yh, yl, xh, xl);

    // layer 2: t = relu(W2 @ s + b2) -> actB hi/lo
    gemm_mma<1><<<ggrid, 256, DYN_SMEM>>>(W2h, W2l, xh, xl, b2, nullptr, yh, yl);

    // layer 3: out = relu(W3 @ t + b3) -> fp32 d_out
    gemm_mma<0><<<ggrid, 256, DYN_SMEM>>>(W3h, W3l, yh, yl, b3, (float*)d_out, nullptr, nullptr);
}

// round 8
// speedup vs baseline: 2.8144x; 1.0619x over previous
#include <cuda_runtime.h>
#include <cuda_bf16.h>

#define CHID   256
#define HWSZ   4096
#define BATCH  16

typedef unsigned int       u32;
typedef unsigned long long u64;
typedef unsigned short     u16;
typedef __nv_bfloat16      bf16;

// ---------------- scratch (device globals) ----------------
__device__ float g_f[BATCH * CHID * HWSZ];  // fp32 h (gemm1 out, dw in)
__device__ u16 g_xh[BATCH * CHID * HWSZ];   // s hi (dw out, gemm2 in)
__device__ u16 g_xl[BATCH * CHID * HWSZ];   // s lo
__device__ u16 g_yh[BATCH * CHID * HWSZ];   // t hi (gemm2 out, gemm3 in)
__device__ u16 g_yl[BATCH * CHID * HWSZ];   // t lo
__device__ u16 g_W1h[CHID * CHID], g_W1l[CHID * CHID];
__device__ u16 g_W2h[CHID * CHID], g_W2l[CHID * CHID];
__device__ u16 g_W3h[CHID * CHID], g_W3l[CHID * CHID];
__device__ float g_b1[CHID], g_b2[CHID], g_b3[CHID];
__device__ float g_Wd[CHID * 81];
__device__ float g_bd[CHID];

// ---------------- helpers ----------------
__device__ __forceinline__ u32 smem_u32(const void* p) {
    u32 a;
    asm("{ .reg .u64 t; cvta.to.shared.u64 t, %1; cvt.u32.u64 %0, t; }" : "=r"(a) : "l"(p));
    return a;
}
__device__ __forceinline__ u16 bf_bits(bf16 v) {
    union { bf16 b; u16 u; } c; c.b = v; return c.u;
}
__device__ __forceinline__ void split_bf(float v, u16& h, u16& l) {
    bf16 hb = __float2bfloat16(v);
    h = bf_bits(hb);
    l = bf_bits(__float2bfloat16(v - __bfloat162float(hb)));
}

__device__ __forceinline__ void cp16(u32 s, const void* g) {
    asm volatile("cp.async.cg.shared.global [%0], [%1], 16;" :: "r"(s), "l"(g) : "memory");
}
__device__ __forceinline__ void cp_commit() {
    asm volatile("cp.async.commit_group;" ::: "memory");
}
template<int N> __device__ __forceinline__ void cp_wait() {
    asm volatile("cp.async.wait_group %0;" :: "n"(N) : "memory");
}

__device__ __forceinline__ void ldsm_x4(u32* r, u32 a) {
    asm volatile("ldmatrix.sync.aligned.m8n8.x4.shared.b16 {%0,%1,%2,%3}, [%4];"
        : "=r"(r[0]), "=r"(r[1]), "=r"(r[2]), "=r"(r[3]) : "r"(a));
}
__device__ __forceinline__ void ldsm_x4_t(u32* r, u32 a) {
    asm volatile("ldmatrix.sync.aligned.m8n8.x4.trans.shared.b16 {%0,%1,%2,%3}, [%4];"
        : "=r"(r[0]), "=r"(r[1]), "=r"(r[2]), "=r"(r[3]) : "r"(a));
}
__device__ __forceinline__ void mma16816(float* c, const u32* a, const u32* b) {
    asm volatile("mma.sync.aligned.m16n8k16.row.col.f32.bf16.bf16.f32 "
        "{%0,%1,%2,%3}, {%4,%5,%6,%7}, {%8,%9}, {%0,%1,%2,%3};"
        : "+f"(c[0]), "+f"(c[1]), "+f"(c[2]), "+f"(c[3])
        : "r"(a[0]), "r"(a[1]), "r"(a[2]), "r"(a[3]), "r"(b[0]), "r"(b[1]));
}

// f32x2 for depthwise
__device__ __forceinline__ u64 pack2(float a, float b) {
    u64 r; asm("mov.b64 %0, {%1, %2};" : "=l"(r) : "f"(a), "f"(b)); return r;
}
__device__ __forceinline__ void unpack2(float& a, float& b, u64 v) {
    asm("mov.b64 {%0, %1}, %2;" : "=f"(a), "=f"(b) : "l"(v));
}
__device__ __forceinline__ u64 ffma2(u64 a, u64 b, u64 c) {
    u64 d; asm("fma.rn.f32x2 %0, %1, %2, %3;" : "=l"(d) : "l"(a), "l"(b), "l"(c)); return d;
}

// ---------------- prep ----------------
__global__ void prep_kernel(
    const float* __restrict__ pre_w,
    const float* __restrict__ bn1_g, const float* __restrict__ bn1_b,
    const float* __restrict__ bn1_m, const float* __restrict__ bn1_v,
    const float* __restrict__ dw3_w, const float* __restrict__ dw3_b,
    const float* __restrict__ dw5_w, const float* __restrict__ dw5_b,
    const float* __restrict__ dw7_w, const float* __restrict__ dw7_b,
    const float* __restrict__ dw9_w, const float* __restrict__ dw9_b,
    const float* __restrict__ pw_w,
    const float* __restrict__ bn2_g, const float* __restrict__ bn2_b,
    const float* __restrict__ bn2_m, const float* __restrict__ bn2_v,
    const float* __restrict__ post_w,
    const float* __restrict__ bn3_g, const float* __restrict__ bn3_b,
    const float* __restrict__ bn3_m, const float* __restrict__ bn3_v)
{
    const int o = blockIdx.x;
    const int i = threadIdx.x;
    const float EPS = 1e-5f;

    const float s1 = __ldg(bn1_g + o) * rsqrtf(__ldg(bn1_v + o) + EPS);
    const float s2 = __ldg(bn2_g + o) * rsqrtf(__ldg(bn2_v + o) + EPS);
    const float s3 = __ldg(bn3_g + o) * rsqrtf(__ldg(bn3_v + o) + EPS);

    split_bf(pre_w [o * CHID + i] * s1, g_W1h[o * CHID + i], g_W1l[o * CHID + i]);
    split_bf(pw_w  [o * CHID + i] * s2, g_W2h[o * CHID + i], g_W2l[o * CHID + i]);
    split_bf(post_w[o * CHID + i] * s3, g_W3h[o * CHID + i], g_W3l[o * CHID + i]);

    if (i < 81) {
        const int y = i / 9, x = i % 9;
        float v = (i == 40) ? 1.0f : 0.0f;
        if (y >= 3 && y <= 5 && x >= 3 && x <= 5) v += dw3_w[o * 9  + (y - 3) * 3 + (x - 3)];
        if (y >= 2 && y <= 6 && x >= 2 && x <= 6) v += dw5_w[o * 25 + (y - 2) * 5 + (x - 2)];
        if (y >= 1 && y <= 7 && x >= 1 && x <= 7) v += dw7_w[o * 49 + (y - 1) * 7 + (x - 1)];
        v += dw9_w[o * 81 + i];
        g_Wd[o * 81 + i] = v;
    }
    if (i == 0) {
        g_b1[o] = bn1_b[o] - bn1_m[o] * s1;
        g_b2[o] = bn2_b[o] - bn2_m[o] * s2;
        g_b3[o] = bn3_b[o] - bn3_m[o] * s3;
        g_bd[o] = dw3_b[o] + dw5_b[o] + dw7_b[o] + dw9_b[o];
    }
}

// ---------------- HMMA GEMM: CTA 128x128, 512 threads, warp tile 32x32 ----------------
// SRC32=1: B operand loaded from fp32 source, split to hi/lo in-register.
#define SA  80                    // A smem row stride bytes
#define SBr 272                   // B smem row stride bytes (128 bf16 + pad)
#define ASZ (128 * SA)            // 10240
#define BSZ (32 * SBr)            // 8704
#define STG (2 * ASZ + 2 * BSZ)   // 37888 per stage
#define DYN_SMEM (2 * STG)        // 75776

// A loader: 128 rows x 32 k, hi+lo; 512 threads -> 1 seg each
__device__ __forceinline__ void load_A(
    u32 sbase, const u16* __restrict__ Wh, const u16* __restrict__ Wl,
    int m0, int k0, int tid)
{
    int row = tid >> 2, seg = tid & 3;
    size_t g = (size_t)(m0 + row) * CHID + k0 + seg * 8;
    u32 so = sbase + row * SA + seg * 16;
    cp16(so, Wh + g);
    cp16(so + ASZ, Wl + g);
}
// B loader (bf16 pair source): 32 rows x 128 cols
__device__ __forceinline__ void load_B16(
    u32 sbase, const u16* __restrict__ Bh, const u16* __restrict__ Bl,
    int n0, int k0, int tid)
{
    int row = tid >> 4, seg = tid & 15;
    size_t g = (size_t)(k0 + row) * HWSZ + n0 + seg * 8;
    u32 so = sbase + 2 * ASZ + row * SBr + seg * 16;
    cp16(so, Bh + g);
    cp16(so + BSZ, Bl + g);
}
// B fp32 source: fetch 8 floats
__device__ __forceinline__ void fetch_B32(
    float* r, const float* __restrict__ Bf, int n0, int k0, int tid)
{
    int row = tid >> 4, seg = tid & 15;
    const float* p = Bf + (size_t)(k0 + row) * HWSZ + n0 + seg * 8;
    *(float4*)(r)     = *(const float4*)(p);
    *(float4*)(r + 4) = *(const float4*)(p + 4);
}
__device__ __forceinline__ void store_B32(
    u32 sbase, const float* r, int tid)
{
    int row = tid >> 4, seg = tid & 15;
    u32 so = sbase + 2 * ASZ + row * SBr + seg * 16;
    ushort4 h0, l0, h1, l1;
    split_bf(r[0], h0.x, l0.x); split_bf(r[1], h0.y, l0.y);
    split_bf(r[2], h0.z, l0.z); split_bf(r[3], h0.w, l0.w);
    split_bf(r[4], h1.x, l1.x); split_bf(r[5], h1.y, l1.y);
    split_bf(r[6], h1.z, l1.z); split_bf(r[7], h1.w, l1.w);
    *(ushort4*)((char*)0 + so)            = h0;   // placeholder, replaced below
    (void)l0; (void)h1; (void)l1;
}

template<int OMODE, int SRC32>   // OMODE 0: fp32 out, 1: bf16 hi/lo out
__global__ __launch_bounds__(512, 1)
void gemm_mma(const u16* __restrict__ Wh, const u16* __restrict__ Wl,
              const float* __restrict__ Xf,
              const u16* __restrict__ Ah, const u16* __restrict__ Al,
              const float* __restrict__ bias,
              float* __restrict__ outF,
              u16* __restrict__ outH, u16* __restrict__ outL)
{
    extern __shared__ __align__(16) char smem[];
    const u32 sb = smem_u32(smem);
    const int tid = threadIdx.x;
    const int lane = tid & 31, w = tid >> 5;
    const int wm = w & 3, wn = w >> 2;     // 4 m-warps x 4 n-warps
    const int n0 = blockIdx.x * 128;
    const int m0 = blockIdx.y * 128;
    const int b  = blockIdx.z;
    const float* Bf = SRC32 ? (Xf + (size_t)b * CHID * HWSZ) : nullptr;
    const u16* Bh = SRC32 ? nullptr : (Ah + (size_t)b * CHID * HWSZ);
    const u16* Bl = SRC32 ? nullptr : (Al + (size_t)b * CHID * HWSZ);

    float acc[2][4][4];
    #pragma unroll
    for (int i = 0; i < 2; i++)
        #pragma unroll
        for (int j = 0; j < 4; j++)
            #pragma unroll
            for (int p = 0; p < 4; p++) acc[i][j][p] = 0.f;

    float bpre[8];
    // prologue: stage 0
    load_A(sb, Wh, Wl, m0, 0, tid);
    if (SRC32) {
        fetch_B32(bpre, Bf, n0, 0, tid);
        // split + store stage 0 B
        {
            int row = tid >> 4, seg = tid & 15;
            u32 so = sb + 2 * ASZ + row * SBr + seg * 16;
            ushort4 h0, l0, h1, l1;
            split_bf(bpre[0], h0.x, l0.x); split_bf(bpre[1], h0.y, l0.y);
            split_bf(bpre[2], h0.z, l0.z); split_bf(bpre[3], h0.w, l0.w);
            split_bf(bpre[4], h1.x, l1.x); split_bf(bpre[5], h1.y, l1.y);
            split_bf(bpre[6], h1.z, l1.z); split_bf(bpre[7], h1.w, l1.w);
            *(ushort4*)(smem + (so - sb))       = h0;
            *(ushort4*)(smem + (so - sb) + 8)   = h1;
            *(ushort4*)(smem + (so - sb) + BSZ)     = l0;
            *(ushort4*)(smem + (so - sb) + BSZ + 8) = l1;
        }
    } else {
        load_B16(sb, Bh, Bl, n0, 0, tid);
    }
    cp_commit();

    const int q  = lane >> 3, lr = lane & 7;
    const int fr = (q & 1) * 8 + lr;
    const int fc = (q >> 1) * 8;

    for (int s = 0; s < 8; s++) {
        if (s < 7) {
            const u32 nb = sb + ((s + 1) & 1) * STG;
            load_A(nb, Wh, Wl, m0, (s + 1) * 32, tid);
            if (SRC32) fetch_B32(bpre, Bf, n0, (s + 1) * 32, tid);
            else       load_B16(nb, Bh, Bl, n0, (s + 1) * 32, tid);
            cp_commit();
            cp_wait<1>();
        } else {
            cp_wait<0>();
        }
        __syncthreads();
        const u32 st = sb + (s & 1) * STG;

        #pragma unroll
        for (int ks = 0; ks < 2; ks++) {
            u32 bh[8], bl[8];
            #pragma unroll
            for (int p = 0; p < 2; p++) {
                u32 ba = st + 2 * ASZ + (ks * 16 + fr) * SBr + (wn * 32 + p * 16 + fc) * 2;
                ldsm_x4_t(bh + p * 4, ba);
                ldsm_x4_t(bl + p * 4, ba + BSZ);
            }
            #pragma unroll
            for (int ms = 0; ms < 2; ms++) {
                u32 ah[4], al[4];
                u32 aa = st + (wm * 32 + ms * 16 + fr) * SA + (ks * 16 + fc) * 2;
                ldsm_x4(ah, aa);
                ldsm_x4(al, aa + ASZ);
                #pragma unroll
                for (int ns = 0; ns < 4; ns++) {
                    const u32* ph = &bh[(ns >> 1) * 4 + (ns & 1) * 2];
                    const u32* pl = &bl[(ns >> 1) * 4 + (ns & 1) * 2];
                    mma16816(acc[ms][ns], ah, ph);
                    mma16816(acc[ms][ns], ah, pl);
                    mma16816(acc[ms][ns], al, ph);
                }
            }
        }

        if (SRC32 && s < 7) {
            // split prefetched fp32 B and store into next stage buffer
            const u32 nb = sb + ((s + 1) & 1) * STG;
            int row = tid >> 4, seg = tid & 15;
            u32 off = (nb - sb) + 2 * ASZ + row * SBr + seg * 16;
            ushort4 h0, l0, h1, l1;
            split_bf(bpre[0], h0.x, l0.x); split_bf(bpre[1], h0.y, l0.y);
            split_bf(bpre[2], h0.z, l0.z); split_bf(bpre[3], h0.w, l0.w);
            split_bf(bpre[4], h1.x, l1.x); split_bf(bpre[5], h1.y, l1.y);
            split_bf(bpre[6], h1.z, l1.z); split_bf(bpre[7], h1.w, l1.w);
            *(ushort4*)(smem + off)           = h0;
            *(ushort4*)(smem + off + 8)       = h1;
            *(ushort4*)(smem + off + BSZ)     = l0;
            *(ushort4*)(smem + off + BSZ + 8) = l1;
        }
        __syncthreads();
    }

    // epilogue: bias + relu
    const int r0 = lane >> 2, c0 = (lane & 3) * 2;
    #pragma unroll
    for (int ms = 0; ms < 2; ms++) {
        const int row = m0 + wm * 32 + ms * 16 + r0;
        const float bv0 = __ldg(bias + row);
        const float bv1 = __ldg(bias + row + 8);
        #pragma unroll
        for (int ns = 0; ns < 4; ns++) {
            const int col = n0 + wn * 32 + ns * 8 + c0;
            float v0 = fmaxf(acc[ms][ns][0] + bv0, 0.f);
            float v1 = fmaxf(acc[ms][ns][1] + bv0, 0.f);
            float v2 = fmaxf(acc[ms][ns][2] + bv1, 0.f);
            float v3 = fmaxf(acc[ms][ns][3] + bv1, 0.f);
            size_t o0 = ((size_t)b * CHID + row) * HWSZ + col;
            size_t o1 = o0 + (size_t)8 * HWSZ;
            if (OMODE == 0) {
                *(float2*)(outF + o0) = make_float2(v0, v1);
                *(float2*)(outF + o1) = make_float2(v2, v3);
            } else {
                ushort2 h0, l0, h1, l1;
                split_bf(v0, h0.x, l0.x); split_bf(v1, h0.y, l0.y);
                split_bf(v2, h1.x, l1.x); split_bf(v3, h1.y, l1.y);
                *(ushort2*)(outH + o0) = h0;
                *(ushort2*)(outL + o0) = l0;
                *(ushort2*)(outH + o1) = h1;
                *(ushort2*)(outL + o1) = l1;
            }
        }
    }
}

// ---------------- depthwise: fp32 in, bf16 hi/lo out; 2 channels per f32x2 lane ----------------
__global__ __launch_bounds__(256)
void dw2(const float* __restrict__ Hf, u16* __restrict__ Sh, u16* __restrict__ Sl)
{
    __shared__ __align__(16) float2 tile[72][72];
    __shared__ __align__(16) float2 w2[81];

    const int cp = blockIdx.x, b = blockIdx.y;
    const int c0 = cp * 2;
    const size_t base0 = ((size_t)b * CHID + c0) * HWSZ;
    const size_t base1 = base0 + HWSZ;
    const int tid = threadIdx.x;

    for (int i = tid; i < 72 * 72; i += 256) ((float2*)tile)[i] = make_float2(0.f, 0.f);
    if (tid < 81) w2[tid] = make_float2(g_Wd[c0 * 81 + tid], g_Wd[(c0 + 1) * 81 + tid]);
    __syncthreads();
    for (int i = tid; i < 1024; i += 256) {
        int y = i >> 4, x4 = (i & 15) << 2;
        float4 a0 = *(const float4*)(Hf + base0 + y * 64 + x4);
        float4 a1 = *(const float4*)(Hf + base1 + y * 64 + x4);
        tile[4 + y][4 + x4 + 0] = make_float2(a0.x, a1.x);
        tile[4 + y][4 + x4 + 1] = make_float2(a0.y, a1.y);
        tile[4 + y][4 + x4 + 2] = make_float2(a0.z, a1.z);
        tile[4 + y][4 + x4 + 3] = make_float2(a0.w, a1.w);
    }
    __syncthreads();

    const int x0 = (tid & 15) * 4;
    const int y0 = (tid >> 4) * 4;
    const u64 bd2 = pack2(g_bd[c0], g_bd[c0 + 1]);
    const u64* wq = (const u64*)w2;

    u64 acc[4][4];
    #pragma unroll
    for (int r = 0; r < 4; r++)
        #pragma unroll
        for (int p = 0; p < 4; p++) acc[r][p] = bd2;

    #pragma unroll
    for (int j = 0; j < 12; j++) {
        u64 rv[12];
        const ulonglong2* rp = (const ulonglong2*)&tile[y0 + j][x0];
        #pragma unroll
        for (int qq = 0; qq < 6; qq++) { ulonglong2 t = rp[qq]; rv[2 * qq] = t.x; rv[2 * qq + 1] = t.y; }
        #pragma unroll
        for (int r = 0; r < 4; r++) {
            const int jj = j - r;
            if (jj >= 0 && jj < 9) {
                #pragma unroll
                for (int i = 0; i < 9; i++) {
                    u64 wv = wq[jj * 9 + i];
                    acc[r][0] = ffma2(wv, rv[i + 0], acc[r][0]);
                    acc[r][1] = ffma2(wv, rv[i + 1], acc[r][1]);
                    acc[r][2] = ffma2(wv, rv[i + 2], acc[r][2]);
                    acc[r][3] = ffma2(wv, rv[i + 3], acc[r][3]);
                }
            }
        }
    }

    #pragma unroll
    for (int r = 0; r < 4; r++) {
        ushort4 h0, l0, h1, l1;
        u16* h0p = (u16*)&h0; u16* l0p = (u16*)&l0;
        u16* h1p = (u16*)&h1; u16* l1p = (u16*)&l1;
        #pragma unroll
        for (int p = 0; p < 4; p++) {
            float v0, v1;
            unpack2(v0, v1, acc[r][p]);
            split_bf(v0, h0p[p], l0p[p]);
            split_bf(v1, h1p[p], l1p[p]);
        }
        size_t o0 = base0 + (y0 + r) * 64 + x0;
        size_t o1 = o0 + HWSZ;
        *(ushort4*)(Sh + o0) = h0;
        *(ushort4*)(Sl + o0) = l0;
        *(ushort4*)(Sh + o1) = h1;
        *(ushort4*)(Sl + o1) = l1;
    }
}

// ---------------- launch ----------------
extern "C" void kernel_launch(void* const* d_in, const int* in_sizes, int n_in,
                              void* d_out, int out_size)
{
    const float* x = (const float*)d_in[0];

    float *fb, *b1, *b2, *b3;
    u16 *xh, *xl, *yh, *yl;
    u16 *W1h, *W1l, *W2h, *W2l, *W3h, *W3l;
    cudaGetSymbolAddress((void**)&fb,  g_f);
    cudaGetSymbolAddress((void**)&xh,  g_xh);
    cudaGetSymbolAddress((void**)&xl,  g_xl);
    cudaGetSymbolAddress((void**)&yh,  g_yh);
    cudaGetSymbolAddress((void**)&yl,  g_yl);
    cudaGetSymbolAddress((void**)&W1h, g_W1h);
    cudaGetSymbolAddress((void**)&W1l, g_W1l);
    cudaGetSymbolAddress((void**)&W2h, g_W2h);
    cudaGetSymbolAddress((void**)&W2l, g_W2l);
    cudaGetSymbolAddress((void**)&W3h, g_W3h);
    cudaGetSymbolAddress((void**)&W3l, g_W3l);
    cudaGetSymbolAddress((void**)&b1,  g_b1);
    cudaGetSymbolAddress((void**)&b2,  g_b2);
    cudaGetSymbolAddress((void**)&b3,  g_b3);

    cudaFuncSetAttribute(gemm_mma<0, 0>, cudaFuncAttributeMaxDynamicSharedMemorySize, DYN_SMEM);
    cudaFuncSetAttribute(gemm_mma<0, 1>, cudaFuncAttributeMaxDynamicSharedMemorySize, DYN_SMEM);
    cudaFuncSetAttribute(gemm_mma<1, 0>, cudaFuncAttributeMaxDynamicSharedMemorySize, DYN_SMEM);

    prep_kernel<<<CHID, 256>>>(
        (const float*)d_in[1], (const float*)d_in[2], (const float*)d_in[3],
        (const float*)d_in[4], (const float*)d_in[5],
        (const float*)d_in[6], (const float*)d_in[7], (const float*)d_in[8],
        (const float*)d_in[9], (const float*)d_in[10], (const float*)d_in[11],
        (const float*)d_in[12], (const float*)d_in[13],
        (const float*)d_in[14], (const float*)d_in[15], (const float*)d_in[16],
        (const float*)d_in[17], (const float*)d_in[18],
        (const float*)d_in[19], (const float*)d_in[20], (const float*)d_in[21],
        (const float*)d_in[22], (const float*)d_in[23]);

    dim3 ggrid(HWSZ / 128, CHID / 128, BATCH);   // (32, 2, 16)

    // layer 1: h = relu(W1 @ x + b1), fp32 x in (split fused), fp32 out
    gemm_mma<0, 1><<<ggrid, 512, DYN_SMEM>>>(W1h, W1l, x, nullptr, nullptr, b1, fb, nullptr, nullptr);

    // depthwise: s = h + sum dw_k(h) + b -> hi/lo
    dim3 dgrid(CHID / 2, BATCH);        // (128, 16)
    dw2<<<dgrid, 256>>>(fb, xh, xl);

    // layer 2: t = relu(W2 @ s + b2) -> hi/lo
    gemm_mma<1, 0><<<ggrid, 512, DYN_SMEM>>>(W2h, W2l, nullptr, xh, xl, b2, nullptr, yh, yl);

    // layer 3: out = relu(W3 @ t + b3) -> fp32 d_out
    gemm_mma<0, 0><<<ggrid, 512, DYN_SMEM>>>(W3h, W3l, nullptr, yh, yl, b3, (float*)d_out, nullptr, nullptr);
}

// round 9
// speedup vs baseline: 3.0545x; 1.0853x over previous
#include <cuda_runtime.h>
#include <cuda_bf16.h>

#define CHID   256
#define HWSZ   4096
#define BATCH  16

typedef unsigned int       u32;
typedef unsigned long long u64;
typedef unsigned short     u16;
typedef __nv_bfloat16      bf16;

// ---------------- scratch (device globals) ----------------
__device__ float g_f[BATCH * CHID * HWSZ];  // fp32 h (gemm1 out, dw in)
__device__ u16 g_xh[BATCH * CHID * HWSZ];   // s hi (dw out, gemm2 in)
__device__ u16 g_xl[BATCH * CHID * HWSZ];   // s lo
__device__ u16 g_yh[BATCH * CHID * HWSZ];   // t hi (gemm2 out, gemm3 in)
__device__ u16 g_yl[BATCH * CHID * HWSZ];   // t lo
__device__ u16 g_W1h[CHID * CHID], g_W1l[CHID * CHID];
__device__ u16 g_W2h[CHID * CHID], g_W2l[CHID * CHID];
__device__ u16 g_W3h[CHID * CHID], g_W3l[CHID * CHID];
__device__ float g_b1[CHID], g_b2[CHID], g_b3[CHID];
__device__ float g_Wd[CHID * 81];
__device__ float g_bd[CHID];

// ---------------- helpers ----------------
__device__ __forceinline__ u32 smem_u32(const void* p) {
    u32 a;
    asm("{ .reg .u64 t; cvta.to.shared.u64 t, %1; cvt.u32.u64 %0, t; }" : "=r"(a) : "l"(p));
    return a;
}
__device__ __forceinline__ u16 bf_bits(bf16 v) {
    union { bf16 b; u16 u; } c; c.b = v; return c.u;
}
__device__ __forceinline__ void split_bf(float v, u16& h, u16& l) {
    bf16 hb = __float2bfloat16(v);
    h = bf_bits(hb);
    l = bf_bits(__float2bfloat16(v - __bfloat162float(hb)));
}

__device__ __forceinline__ void cp16(u32 s, const void* g) {
    asm volatile("cp.async.cg.shared.global [%0], [%1], 16;" :: "r"(s), "l"(g) : "memory");
}
__device__ __forceinline__ void cp_commit() {
    asm volatile("cp.async.commit_group;" ::: "memory");
}
template<int N> __device__ __forceinline__ void cp_wait() {
    asm volatile("cp.async.wait_group %0;" :: "n"(N) : "memory");
}

__device__ __forceinline__ void ldsm_x4(u32* r, u32 a) {
    asm volatile("ldmatrix.sync.aligned.m8n8.x4.shared.b16 {%0,%1,%2,%3}, [%4];"
        : "=r"(r[0]), "=r"(r[1]), "=r"(r[2]), "=r"(r[3]) : "r"(a));
}
__device__ __forceinline__ void ldsm_x4_t(u32* r, u32 a) {
    asm volatile("ldmatrix.sync.aligned.m8n8.x4.trans.shared.b16 {%0,%1,%2,%3}, [%4];"
        : "=r"(r[0]), "=r"(r[1]), "=r"(r[2]), "=r"(r[3]) : "r"(a));
}
__device__ __forceinline__ void mma16816(float* c, const u32* a, const u32* b) {
    asm volatile("mma.sync.aligned.m16n8k16.row.col.f32.bf16.bf16.f32 "
        "{%0,%1,%2,%3}, {%4,%5,%6,%7}, {%8,%9}, {%0,%1,%2,%3};"
        : "+f"(c[0]), "+f"(c[1]), "+f"(c[2]), "+f"(c[3])
        : "r"(a[0]), "r"(a[1]), "r"(a[2]), "r"(a[3]), "r"(b[0]), "r"(b[1]));
}

// f32x2 for depthwise
__device__ __forceinline__ u64 pack2(float a, float b) {
    u64 r; asm("mov.b64 %0, {%1, %2};" : "=l"(r) : "f"(a), "f"(b)); return r;
}
__device__ __forceinline__ void unpack2(float& a, float& b, u64 v) {
    asm("mov.b64 {%0, %1}, %2;" : "=f"(a), "=f"(b) : "l"(v));
}
__device__ __forceinline__ u64 ffma2(u64 a, u64 b, u64 c) {
    u64 d; asm("fma.rn.f32x2 %0, %1, %2, %3;" : "=l"(d) : "l"(a), "l"(b), "l"(c)); return d;
}

// ---------------- prep ----------------
__global__ void prep_kernel(
    const float* __restrict__ pre_w,
    const float* __restrict__ bn1_g, const float* __restrict__ bn1_b,
    const float* __restrict__ bn1_m, const float* __restrict__ bn1_v,
    const float* __restrict__ dw3_w, const float* __restrict__ dw3_b,
    const float* __restrict__ dw5_w, const float* __restrict__ dw5_b,
    const float* __restrict__ dw7_w, const float* __restrict__ dw7_b,
    const float* __restrict__ dw9_w, const float* __restrict__ dw9_b,
    const float* __restrict__ pw_w,
    const float* __restrict__ bn2_g, const float* __restrict__ bn2_b,
    const float* __restrict__ bn2_m, const float* __restrict__ bn2_v,
    const float* __restrict__ post_w,
    const float* __restrict__ bn3_g, const float* __restrict__ bn3_b,
    const float* __restrict__ bn3_m, const float* __restrict__ bn3_v)
{
    const int o = blockIdx.x;
    const int i = threadIdx.x;
    const float EPS = 1e-5f;

    const float s1 = __ldg(bn1_g + o) * rsqrtf(__ldg(bn1_v + o) + EPS);
    const float s2 = __ldg(bn2_g + o) * rsqrtf(__ldg(bn2_v + o) + EPS);
    const float s3 = __ldg(bn3_g + o) * rsqrtf(__ldg(bn3_v + o) + EPS);

    split_bf(pre_w [o * CHID + i] * s1, g_W1h[o * CHID + i], g_W1l[o * CHID + i]);
    split_bf(pw_w  [o * CHID + i] * s2, g_W2h[o * CHID + i], g_W2l[o * CHID + i]);
    split_bf(post_w[o * CHID + i] * s3, g_W3h[o * CHID + i], g_W3l[o * CHID + i]);

    if (i < 81) {
        const int y = i / 9, x = i % 9;
        float v = (i == 40) ? 1.0f : 0.0f;
        if (y >= 3 && y <= 5 && x >= 3 && x <= 5) v += dw3_w[o * 9  + (y - 3) * 3 + (x - 3)];
        if (y >= 2 && y <= 6 && x >= 2 && x <= 6) v += dw5_w[o * 25 + (y - 2) * 5 + (x - 2)];
        if (y >= 1 && y <= 7 && x >= 1 && x <= 7) v += dw7_w[o * 49 + (y - 1) * 7 + (x - 1)];
        v += dw9_w[o * 81 + i];
        g_Wd[o * 81 + i] = v;
    }
    if (i == 0) {
        g_b1[o] = bn1_b[o] - bn1_m[o] * s1;
        g_b2[o] = bn2_b[o] - bn2_m[o] * s2;
        g_b3[o] = bn3_b[o] - bn3_m[o] * s3;
        g_bd[o] = dw3_b[o] + dw5_b[o] + dw7_b[o] + dw9_b[o];
    }
}

// ---------------- HMMA GEMM: CTA 128x128, 512 threads, BK=64, ring-3, 1 sync/stage ----------------
#define SA   144                  // A smem row stride bytes (64 bf16 + pad)
#define SBr  272                  // B smem row stride bytes (128 bf16 + pad)
#define ASZ  (128 * SA)           // 18432
#define BSZ  (64 * SBr)           // 17408
#define STG  (2 * ASZ + 2 * BSZ)  // 71680 per stage
#define NSTAGE 3
#define DYN_SMEM (NSTAGE * STG)   // 215040

// A: 128 rows x 64 k (hi+lo), 512 threads -> 2 segs each
__device__ __forceinline__ void load_A(
    u32 sbase, const u16* __restrict__ Wh, const u16* __restrict__ Wl,
    int m0, int k0, int tid)
{
    #pragma unroll
    for (int i = 0; i < 2; i++) {
        int u = tid + i * 512;
        int row = u >> 3, seg = u & 7;
        size_t g = (size_t)(m0 + row) * CHID + k0 + seg * 8;
        u32 so = sbase + row * SA + seg * 16;
        cp16(so, Wh + g);
        cp16(so + ASZ, Wl + g);
    }
}
// B (bf16 pair source): 64 rows x 128 cols (hi+lo)
__device__ __forceinline__ void load_B16(
    u32 sbase, const u16* __restrict__ Bh, const u16* __restrict__ Bl,
    int n0, int k0, int tid)
{
    #pragma unroll
    for (int i = 0; i < 2; i++) {
        int u = tid + i * 512;
        int row = u >> 4, seg = u & 15;
        size_t g = (size_t)(k0 + row) * HWSZ + n0 + seg * 8;
        u32 so = sbase + 2 * ASZ + row * SBr + seg * 16;
        cp16(so, Bh + g);
        cp16(so + BSZ, Bl + g);
    }
}
// B fp32 source: fetch 16 floats into regs
__device__ __forceinline__ void fetch_B32(
    float* r, const float* __restrict__ Bf, int n0, int k0, int tid)
{
    #pragma unroll
    for (int i = 0; i < 2; i++) {
        int u = tid + i * 512;
        int row = u >> 4, seg = u & 15;
        const float* p = Bf + (size_t)(k0 + row) * HWSZ + n0 + seg * 8;
        *(float4*)(r + i * 8)     = *(const float4*)(p);
        *(float4*)(r + i * 8 + 4) = *(const float4*)(p + 4);
    }
}
// split 16 floats -> hi/lo bf16, store into stage buffer (byte offset rel)
__device__ __forceinline__ void store_B32(
    char* smem, u32 rel, const float* r, int tid)
{
    #pragma unroll
    for (int i = 0; i < 2; i++) {
        int u = tid + i * 512;
        int row = u >> 4, seg = u & 15;
        u32 off = rel + 2 * ASZ + row * SBr + seg * 16;
        ushort4 h0, l0, h1, l1;
        split_bf(r[i*8+0], h0.x, l0.x); split_bf(r[i*8+1], h0.y, l0.y);
        split_bf(r[i*8+2], h0.z, l0.z); split_bf(r[i*8+3], h0.w, l0.w);
        split_bf(r[i*8+4], h1.x, l1.x); split_bf(r[i*8+5], h1.y, l1.y);
        split_bf(r[i*8+6], h1.z, l1.z); split_bf(r[i*8+7], h1.w, l1.w);
        *(ushort4*)(smem + off)           = h0;
        *(ushort4*)(smem + off + 8)       = h1;
        *(ushort4*)(smem + off + BSZ)     = l0;
        *(ushort4*)(smem + off + BSZ + 8) = l1;
    }
}

template<int OMODE, int SRC32>   // OMODE 0: fp32 out, 1: bf16 hi/lo out
__global__ __launch_bounds__(512, 1)
void gemm_mma(const u16* __restrict__ Wh, const u16* __restrict__ Wl,
              const float* __restrict__ Xf,
              const u16* __restrict__ Ah, const u16* __restrict__ Al,
              const float* __restrict__ bias,
              float* __restrict__ outF,
              u16* __restrict__ outH, u16* __restrict__ outL)
{
    extern __shared__ __align__(16) char smem[];
    const u32 sb = smem_u32(smem);
    const int tid = threadIdx.x;
    const int lane = tid & 31, w = tid >> 5;
    const int wm = w & 3, wn = w >> 2;     // 4 m-warps x 4 n-warps
    const int n0 = blockIdx.x * 128;
    const int m0 = blockIdx.y * 128;
    const int b  = blockIdx.z;
    const float* Bf = SRC32 ? (Xf + (size_t)b * CHID * HWSZ) : nullptr;
    const u16* Bh = SRC32 ? nullptr : (Ah + (size_t)b * CHID * HWSZ);
    const u16* Bl = SRC32 ? nullptr : (Al + (size_t)b * CHID * HWSZ);

    float acc[2][4][4];
    #pragma unroll
    for (int i = 0; i < 2; i++)
        #pragma unroll
        for (int j = 0; j < 4; j++)
            #pragma unroll
            for (int p = 0; p < 4; p++) acc[i][j][p] = 0.f;

    float bpre[16];

    // prologue: stages 0 and 1
    load_A(sb, Wh, Wl, m0, 0, tid);
    if (SRC32) { fetch_B32(bpre, Bf, n0, 0, tid); store_B32(smem, 0, bpre, tid); }
    else       load_B16(sb, Bh, Bl, n0, 0, tid);
    cp_commit();
    load_A(sb + STG, Wh, Wl, m0, 64, tid);
    if (SRC32) { fetch_B32(bpre, Bf, n0, 64, tid); store_B32(smem, STG, bpre, tid); }
    else       load_B16(sb + STG, Bh, Bl, n0, 64, tid);
    cp_commit();

    const int q  = lane >> 3, lr = lane & 7;
    const int fr = (q & 1) * 8 + lr;
    const int fc = (q >> 1) * 8;

    #pragma unroll
    for (int s = 0; s < 4; s++) {
        if (s < 3) cp_wait<1>(); else cp_wait<0>();
        __syncthreads();                       // single barrier per stage

        if (s < 2) {                           // load stage s+2 into ring buffer
            const int nbuf = (s + 2) % NSTAGE;
            load_A(sb + nbuf * STG, Wh, Wl, m0, (s + 2) * 64, tid);
            if (!SRC32) load_B16(sb + nbuf * STG, Bh, Bl, n0, (s + 2) * 64, tid);
            cp_commit();
            if (SRC32) fetch_B32(bpre, Bf, n0, (s + 2) * 64, tid);
        }

        const u32 st = sb + (s % NSTAGE) * STG;
        #pragma unroll
        for (int ks = 0; ks < 4; ks++) {
            u32 bh[8], bl[8];
            #pragma unroll
            for (int p = 0; p < 2; p++) {
                u32 ba = st + 2 * ASZ + (ks * 16 + fr) * SBr + (wn * 32 + p * 16 + fc) * 2;
                ldsm_x4_t(bh + p * 4, ba);
                ldsm_x4_t(bl + p * 4, ba + BSZ);
            }
            #pragma unroll
            for (int ms = 0; ms < 2; ms++) {
                u32 ah[4], al[4];
                u32 aa = st + (wm * 32 + ms * 16 + fr) * SA + (ks * 16 + fc) * 2;
                ldsm_x4(ah, aa);
                ldsm_x4(al, aa + ASZ);
                #pragma unroll
                for (int ns = 0; ns < 4; ns++) {
                    const u32* ph = &bh[(ns >> 1) * 4 + (ns & 1) * 2];
                    const u32* pl = &bl[(ns >> 1) * 4 + (ns & 1) * 2];
                    mma16816(acc[ms][ns], ah, ph);
                    mma16816(acc[ms][ns], ah, pl);
                    mma16816(acc[ms][ns], al, ph);
                }
            }
        }

        if (SRC32 && s < 2)                    // split prefetched fp32, store to ring buffer
            store_B32(smem, ((s + 2) % NSTAGE) * STG, bpre, tid);
    }

    // epilogue: bias + relu
    const int r0 = lane >> 2, c0 = (lane & 3) * 2;
    #pragma unroll
    for (int ms = 0; ms < 2; ms++) {
        const int row = m0 + wm * 32 + ms * 16 + r0;
        const float bv0 = __ldg(bias + row);
        const float bv1 = __ldg(bias + row + 8);
        #pragma unroll
        for (int ns = 0; ns < 4; ns++) {
            const int col = n0 + wn * 32 + ns * 8 + c0;
            float v0 = fmaxf(acc[ms][ns][0] + bv0, 0.f);
            float v1 = fmaxf(acc[ms][ns][1] + bv0, 0.f);
            float v2 = fmaxf(acc[ms][ns][2] + bv1, 0.f);
            float v3 = fmaxf(acc[ms][ns][3] + bv1, 0.f);
            size_t o0 = ((size_t)b * CHID + row) * HWSZ + col;
            size_t o1 = o0 + (size_t)8 * HWSZ;
            if (OMODE == 0) {
                *(float2*)(outF + o0) = make_float2(v0, v1);
                *(float2*)(outF + o1) = make_float2(v2, v3);
            } else {
                ushort2 h0, l0, h1, l1;
                split_bf(v0, h0.x, l0.x); split_bf(v1, h0.y, l0.y);
                split_bf(v2, h1.x, l1.x); split_bf(v3, h1.y, l1.y);
                *(ushort2*)(outH + o0) = h0;
                *(ushort2*)(outL + o0) = l0;
                *(ushort2*)(outH + o1) = h1;
                *(ushort2*)(outL + o1) = l1;
            }
        }
    }
}

// ---------------- depthwise: fp32 in, bf16 hi/lo out; 2 channels per f32x2 lane ----------------
__global__ __launch_bounds__(256)
void dw2(const float* __restrict__ Hf, u16* __restrict__ Sh, u16* __restrict__ Sl)
{
    __shared__ __align__(16) float2 tile[72][72];
    __shared__ __align__(16) float2 w2[81];

    const int cp = blockIdx.x, b = blockIdx.y;
    const int c0 = cp * 2;
    const size_t base0 = ((size_t)b * CHID + c0) * HWSZ;
    const size_t base1 = base0 + HWSZ;
    const int tid = threadIdx.x;

    for (int i = tid; i < 72 * 72; i += 256) ((float2*)tile)[i] = make_float2(0.f, 0.f);
    if (tid < 81) w2[tid] = make_float2(g_Wd[c0 * 81 + tid], g_Wd[(c0 + 1) * 81 + tid]);
    __syncthreads();
    for (int i = tid; i < 1024; i += 256) {
        int y = i >> 4, x4 = (i & 15) << 2;
        float4 a0 = *(const float4*)(Hf + base0 + y * 64 + x4);
        float4 a1 = *(const float4*)(Hf + base1 + y * 64 + x4);
        tile[4 + y][4 + x4 + 0] = make_float2(a0.x, a1.x);
        tile[4 + y][4 + x4 + 1] = make_float2(a0.y, a1.y);
        tile[4 + y][4 + x4 + 2] = make_float2(a0.z, a1.z);
        tile[4 + y][4 + x4 + 3] = make_float2(a0.w, a1.w);
    }
    __syncthreads();

    const int x0 = (tid & 15) * 4;
    const int y0 = (tid >> 4) * 4;
    const u64 bd2 = pack2(g_bd[c0], g_bd[c0 + 1]);
    const u64* wq = (const u64*)w2;

    u64 acc[4][4];
    #pragma unroll
    for (int r = 0; r < 4; r++)
        #pragma unroll
        for (int p = 0; p < 4; p++) acc[r][p] = bd2;

    #pragma unroll
    for (int j = 0; j < 12; j++) {
        u64 rv[12];
        const ulonglong2* rp = (const ulonglong2*)&tile[y0 + j][x0];
        #pragma unroll
        for (int qq = 0; qq < 6; qq++) { ulonglong2 t = rp[qq]; rv[2 * qq] = t.x; rv[2 * qq + 1] = t.y; }
        #pragma unroll
        for (int r = 0; r < 4; r++) {
            const int jj = j - r;
            if (jj >= 0 && jj < 9) {
                #pragma unroll
                for (int i = 0; i < 9; i++) {
                    u64 wv = wq[jj * 9 + i];
                    acc[r][0] = ffma2(wv, rv[i + 0], acc[r][0]);
                    acc[r][1] = ffma2(wv, rv[i + 1], acc[r][1]);
                    acc[r][2] = ffma2(wv, rv[i + 2], acc[r][2]);
                    acc[r][3] = ffma2(wv, rv[i + 3], acc[r][3]);
                }
            }
        }
    }

    #pragma unroll
    for (int r = 0; r < 4; r++) {
        ushort4 h0, l0, h1, l1;
        u16* h0p = (u16*)&h0; u16* l0p = (u16*)&l0;
        u16* h1p = (u16*)&h1; u16* l1p = (u16*)&l1;
        #pragma unroll
        for (int p = 0; p < 4; p++) {
            float v0, v1;
            unpack2(v0, v1, acc[r][p]);
            split_bf(v0, h0p[p], l0p[p]);
            split_bf(v1, h1p[p], l1p[p]);
        }
        size_t o0 = base0 + (y0 + r) * 64 + x0;
        size_t o1 = o0 + HWSZ;
        *(ushort4*)(Sh + o0) = h0;
        *(ushort4*)(Sl + o0) = l0;
        *(ushort4*)(Sh + o1) = h1;
        *(ushort4*)(Sl + o1) = l1;
    }
}

// ---------------- launch ----------------
extern "C" void kernel_launch(void* const* d_in, const int* in_sizes, int n_in,
                              void* d_out, int out_size)
{
    const float* x = (const float*)d_in[0];

    float *fb, *b1, *b2, *b3;
    u16 *xh, *xl, *yh, *yl;
    u16 *W1h, *W1l, *W2h, *W2l, *W3h, *W3l;
    cudaGetSymbolAddress((void**)&fb,  g_f);
    cudaGetSymbolAddress((void**)&xh,  g_xh);
    cudaGetSymbolAddress((void**)&xl,  g_xl);
    cudaGetSymbolAddress((void**)&yh,  g_yh);
    cudaGetSymbolAddress((void**)&yl,  g_yl);
    cudaGetSymbolAddress((void**)&W1h, g_W1h);
    cudaGetSymbolAddress((void**)&W1l, g_W1l);
    cudaGetSymbolAddress((void**)&W2h, g_W2h);
    cudaGetSymbolAddress((void**)&W2l, g_W2l);
    cudaGetSymbolAddress((void**)&W3h, g_W3h);
    cudaGetSymbolAddress((void**)&W3l, g_W3l);
    cudaGetSymbolAddress((void**)&b1,  g_b1);
    cudaGetSymbolAddress((void**)&b2,  g_b2);
    cudaGetSymbolAddress((void**)&b3,  g_b3);

    cudaFuncSetAttribute(gemm_mma<0, 0>, cudaFuncAttributeMaxDynamicSharedMemorySize, DYN_SMEM);
    cudaFuncSetAttribute(gemm_mma<0, 1>, cudaFuncAttributeMaxDynamicSharedMemorySize, DYN_SMEM);
    cudaFuncSetAttribute(gemm_mma<1, 0>, cudaFuncAttributeMaxDynamicSharedMemorySize, DYN_SMEM);

    prep_kernel<<<CHID, 256>>>(
        (const float*)d_in[1], (const float*)d_in[2], (const float*)d_in[3],
        (const float*)d_in[4], (const float*)d_in[5],
        (const float*)d_in[6], (const float*)d_in[7], (const float*)d_in[8],
        (const float*)d_in[9], (const float*)d_in[10], (const float*)d_in[11],
        (const float*)d_in[12], (const float*)d_in[13],
        (const float*)d_in[14], (const float*)d_in[15], (const float*)d_in[16],
        (const float*)d_in[17], (const float*)d_in[18],
        (const float*)d_in[19], (const float*)d_in[20], (const float*)d_in[21],
        (const float*)d_in[22], (const float*)d_in[23]);

    dim3 ggrid(HWSZ / 128, CHID / 128, BATCH);   // (32, 2, 16)

    // layer 1: h = relu(W1 @ x + b1), fp32 x in (split fused), fp32 out
    gemm_mma<0, 1><<<ggrid, 512, DYN_SMEM>>>(W1h, W1l, x, nullptr, nullptr, b1, fb, nullptr, nullptr);

    // depthwise: s = h + sum dw_k(h) + b -> hi/lo
    dim3 dgrid(CHID / 2, BATCH);        // (128, 16)
    dw2<<<dgrid, 256>>>(fb, xh, xl);

    // layer 2: t = relu(W2 @ s + b2) -> hi/lo
    gemm_mma<1, 0><<<ggrid, 512, DYN_SMEM>>>(W2h, W2l, nullptr, xh, xl, b2, nullptr, yh, yl);

    // layer 3: out = relu(W3 @ t + b3) -> fp32 d_out
    gemm_mma<0, 0><<<ggrid, 512, DYN_SMEM>>>(W3h, W3l, nullptr, yh, yl, b3, (float*)d_out, nullptr, nullptr);
}